// round 1
// baseline (speedup 1.0000x reference)
#include <cuda_runtime.h>
#include <cuda_bf16.h>
#include <math.h>

// ---------------- problem constants ----------------
#define EMB      1024
#define N_HEADS  16
#define N_KV     4
#define HEAD_DIM 128
#define N_EXP    8
#define TOP_K    2
#define MOE_HID  1024
#define BATCH    2
#define SEQ      2048
#define T_TOK    (BATCH*SEQ)          // 4096
#define QDIM     (N_HEADS*HEAD_DIM)   // 2048
#define KVDIM    (N_KV*HEAD_DIM)      // 512
#define N_SLOT   (T_TOK*TOP_K)        // 8192
#define EPSV     1e-6f

// ---------------- scratch (device globals; no allocation allowed) ----------------
__device__ float g_h1[T_TOK*EMB];
__device__ float g_q [T_TOK*QDIM];
__device__ float g_k [T_TOK*KVDIM];
__device__ float g_v [T_TOK*KVDIM];
__device__ float g_ctx[T_TOK*QDIM];
__device__ float g_x1[T_TOK*EMB];
__device__ float g_h2[T_TOK*EMB];
__device__ float g_gu[N_SLOT*2*MOE_HID];
__device__ float g_act[N_SLOT*MOE_HID];
__device__ float g_outslot[N_SLOT*EMB];
__device__ int   g_topk_idx[N_SLOT];
__device__ float g_topk_w[N_SLOT];
__device__ int   g_counts[N_EXP];
__device__ int   g_off[N_EXP];
__device__ int   g_cursor[N_EXP];
__device__ int   g_slot_token[N_SLOT];
__device__ int   g_slot_of[N_SLOT];

// ---------------- block reduce (sum, broadcast to all threads) ----------------
__device__ __forceinline__ float blockReduceSum(float v) {
    __shared__ float sh[32];
    int lane = threadIdx.x & 31;
    int wid  = threadIdx.x >> 5;
    int nw   = blockDim.x >> 5;
    #pragma unroll
    for (int o = 16; o; o >>= 1) v += __shfl_xor_sync(0xffffffffu, v, o);
    if (lane == 0) sh[wid] = v;
    __syncthreads();
    if (threadIdx.x == 0) {
        float s = 0.f;
        for (int i = 0; i < nw; i++) s += sh[i];
        sh[0] = s;
    }
    __syncthreads();
    float r = sh[0];
    __syncthreads();
    return r;
}

// ---------------- RMSNorm over EMB=1024 (one block per token, 256 thr) ----------------
__global__ void rmsnorm_kernel(const float* __restrict__ x, const float* __restrict__ w,
                               float* __restrict__ o) {
    int t = blockIdx.x;
    int d4 = threadIdx.x * 4;
    const float* xr = x + (long long)t * EMB;
    float4 v = *(const float4*)(xr + d4);
    float ss = v.x*v.x + v.y*v.y + v.z*v.z + v.w*v.w;
    ss = blockReduceSum(ss);
    float scale = rsqrtf(ss * (1.0f / EMB) + EPSV);
    float4 wv = *(const float4*)(w + d4);
    float4 r;
    r.x = v.x*scale*wv.x; r.y = v.y*scale*wv.y;
    r.z = v.z*scale*wv.z; r.w = v.w*scale*wv.w;
    *(float4*)(o + (long long)t * EMB + d4) = r;
}

// ---------------- per-head RMSNorm + RoPE (in place). grid(T, H), 128 thr ----------------
__global__ void qknorm_rope_kernel(float* __restrict__ qk, const float* __restrict__ w,
                                   const int* __restrict__ pos_ids, int H) {
    int t = blockIdx.x, h = blockIdx.y, d = threadIdx.x;
    float* base = qk + ((long long)t * H + h) * HEAD_DIM;
    float v = base[d];
    float ss = blockReduceSum(v * v);
    float scale = rsqrtf(ss * (1.0f / HEAD_DIM) + EPSV);
    float nv = v * scale * w[d];
    __shared__ float sh[HEAD_DIM];
    sh[d] = nv;
    __syncthreads();
    int s = t & (SEQ - 1);
    float pos = (float)pos_ids[s];
    int i = d & 63;
    // inv_freq = 10000^(-2i/128) = 2^(-i * log2(10000)/64)
    float inv = exp2f(-(float)i * (13.287712379549449f / 64.0f));
    float ang = pos * inv;
    float sn, cs;
    sincosf(ang, &sn, &cs);
    float other = (d < 64) ? -sh[d + 64] : sh[d - 64];
    base[d] = nv * cs + other * sn;
}

// ---------------- generic fp32 GEMM: C[M,N] = gather(A)[M,K] * B[N,K]^T (+res) ----------------
// Supports per-expert segmentation (seg_off/seg_cnt, blockIdx.z = expert) and row gather.
#define BM 64
#define BN 64
#define BK 16
__global__ __launch_bounds__(256)
void gemm_kernel(const float* __restrict__ A, const float* __restrict__ Bsrc,
                 float* __restrict__ C, int Mtotal, int N, int K,
                 const float* __restrict__ addres,
                 const int* __restrict__ seg_off, const int* __restrict__ seg_cnt,
                 const int* __restrict__ rowidx, long long strideB) {
    __shared__ float As[BK][BM];
    __shared__ float Bs[BK][BN];
    int z = blockIdx.z;
    int mbase = 0, mcnt = Mtotal;
    if (seg_off) { mbase = seg_off[z]; mcnt = seg_cnt[z]; }
    int tm0 = blockIdx.y * BM;
    if (tm0 >= mcnt) return;
    int tn0 = blockIdx.x * BN;
    const float* Bp = Bsrc + (long long)z * strideB;

    int tid = threadIdx.x;
    int lr = tid >> 2;          // 0..63 row in tile (for loads)
    int lk = (tid & 3) << 2;    // 0,4,8,12

    int lrow = tm0 + lr;
    bool avalid = (lrow < mcnt);
    long long arow = 0;
    if (avalid) arow = rowidx ? (long long)rowidx[mbase + lrow] : (long long)(mbase + lrow);
    const float* Aload = A + arow * (long long)K;
    const float* Bload = Bp + (long long)(tn0 + lr) * K;

    int rm = (tid >> 4) << 2;
    int cn = (tid & 15) << 2;

    float acc[4][4];
    #pragma unroll
    for (int i = 0; i < 4; i++)
        #pragma unroll
        for (int j = 0; j < 4; j++) acc[i][j] = 0.f;

    for (int k0 = 0; k0 < K; k0 += BK) {
        float4 av = avalid ? *(const float4*)(Aload + k0 + lk) : make_float4(0,0,0,0);
        float4 bv = *(const float4*)(Bload + k0 + lk);
        As[lk+0][lr] = av.x; As[lk+1][lr] = av.y; As[lk+2][lr] = av.z; As[lk+3][lr] = av.w;
        Bs[lk+0][lr] = bv.x; Bs[lk+1][lr] = bv.y; Bs[lk+2][lr] = bv.z; Bs[lk+3][lr] = bv.w;
        __syncthreads();
        #pragma unroll
        for (int kk = 0; kk < BK; kk++) {
            float4 a4 = *(const float4*)&As[kk][rm];
            float4 b4 = *(const float4*)&Bs[kk][cn];
            float ar[4] = {a4.x, a4.y, a4.z, a4.w};
            float br[4] = {b4.x, b4.y, b4.z, b4.w};
            #pragma unroll
            for (int i = 0; i < 4; i++)
                #pragma unroll
                for (int j = 0; j < 4; j++) acc[i][j] = fmaf(ar[i], br[j], acc[i][j]);
        }
        __syncthreads();
    }
    #pragma unroll
    for (int i = 0; i < 4; i++) {
        int lm = tm0 + rm + i;
        if (lm < mcnt) {
            long long off = ((long long)(mbase + lm)) * N + tn0 + cn;
            float4 r = make_float4(acc[i][0], acc[i][1], acc[i][2], acc[i][3]);
            if (addres) {
                float4 rs = *(const float4*)(addres + off);
                r.x += rs.x; r.y += rs.y; r.z += rs.z; r.w += rs.w;
            }
            *(float4*)(C + off) = r;
        }
    }
}

// ---------------- attention: causal GQA flash-style, 4 q-rows per 128-thr block ----------------
#define QT 4
#define KT 32
__global__ __launch_bounds__(128)
void attn_kernel(const float* __restrict__ Q, const float* __restrict__ K,
                 const float* __restrict__ V, float* __restrict__ ctx) {
    int q0 = blockIdx.x * QT;
    int h  = blockIdx.y;
    int b  = blockIdx.z;
    int tid = threadIdx.x;

    __shared__ float qs[QT][HEAD_DIM];
    __shared__ float Ks[KT][HEAD_DIM + 4];
    __shared__ float Vs[KT][HEAD_DIM + 4];
    __shared__ float sc[QT][KT];
    __shared__ float ps[QT][KT];

    const float scale = 0.08838834764831845f; // 1/sqrt(128)
    long long trow0 = (long long)b * SEQ + q0;
    #pragma unroll
    for (int qi = 0; qi < QT; qi++)
        qs[qi][tid] = Q[(trow0 + qi) * QDIM + h * HEAD_DIM + tid] * scale;

    int kvh = h >> 2;
    const float* Kbase = K + (long long)b * SEQ * KVDIM + kvh * HEAD_DIM;
    const float* Vbase = V + (long long)b * SEQ * KVDIM + kvh * HEAD_DIM;

    float m[QT], l[QT], acc[QT];
    #pragma unroll
    for (int qi = 0; qi < QT; qi++) { m[qi] = -1e30f; l[qi] = 0.f; acc[qi] = 0.f; }

    int qmax = q0 + QT - 1;
    int r0 = tid >> 5;          // 0..3
    int c0 = (tid & 31) << 2;   // col*4
    int j  = tid >> 2;          // key 0..31
    int qt = tid & 3;           // dim quarter

    for (int t0 = 0; t0 <= qmax; t0 += KT) {
        __syncthreads();
        #pragma unroll
        for (int i = 0; i < 8; i++) {
            int r = i * 4 + r0;
            long long kg = t0 + r;  // always < SEQ
            *(float4*)&Ks[r][c0] = *(const float4*)(Kbase + kg * KVDIM + c0);
            *(float4*)&Vs[r][c0] = *(const float4*)(Vbase + kg * KVDIM + c0);
        }
        __syncthreads();

        // scores: 4 threads per key, each does a 32-dim partial for all QT rows
        {
            float p[QT] = {0.f, 0.f, 0.f, 0.f};
            const float* kr = &Ks[j][qt * 32];
            #pragma unroll
            for (int dd = 0; dd < 32; dd += 4) {
                float4 k4 = *(const float4*)(kr + dd);
                #pragma unroll
                for (int qi = 0; qi < QT; qi++) {
                    float4 q4 = *(const float4*)(&qs[qi][qt * 32 + dd]);
                    p[qi] += k4.x*q4.x + k4.y*q4.y + k4.z*q4.z + k4.w*q4.w;
                }
            }
            #pragma unroll
            for (int qi = 0; qi < QT; qi++) {
                p[qi] += __shfl_xor_sync(0xffffffffu, p[qi], 1);
                p[qi] += __shfl_xor_sync(0xffffffffu, p[qi], 2);
            }
            if (qt == 0) {
                #pragma unroll
                for (int qi = 0; qi < QT; qi++)
                    sc[qi][j] = (t0 + j <= q0 + qi) ? p[qi] : -1e30f;
            }
        }
        __syncthreads();

        float newm[QT], f[QT];
        #pragma unroll
        for (int qi = 0; qi < QT; qi++) {
            float tmax = -1e30f;
            #pragma unroll
            for (int jj = 0; jj < KT; jj++) tmax = fmaxf(tmax, sc[qi][jj]);
            newm[qi] = fmaxf(m[qi], tmax);
            f[qi] = expf(m[qi] - newm[qi]);
        }
        if (tid < KT) {
            #pragma unroll
            for (int qi = 0; qi < QT; qi++)
                ps[qi][tid] = expf(sc[qi][tid] - newm[qi]);
        }
        __syncthreads();
        #pragma unroll
        for (int qi = 0; qi < QT; qi++) { acc[qi] *= f[qi]; l[qi] *= f[qi]; m[qi] = newm[qi]; }
        #pragma unroll
        for (int jj = 0; jj < KT; jj++) {
            float vv = Vs[jj][tid];
            #pragma unroll
            for (int qi = 0; qi < QT; qi++) {
                float pk = ps[qi][jj];
                l[qi] += pk;
                acc[qi] = fmaf(pk, vv, acc[qi]);
            }
        }
    }
    #pragma unroll
    for (int qi = 0; qi < QT; qi++)
        ctx[(trow0 + qi) * QDIM + h * HEAD_DIM + tid] = acc[qi] / l[qi];
}

// ---------------- MoE routing ----------------
__global__ void reset_kernel() {
    if (threadIdx.x < N_EXP) g_counts[threadIdx.x] = 0;
}

__global__ void router_kernel(const float* __restrict__ h, const float* __restrict__ rw) {
    int warp = threadIdx.x >> 5, lane = threadIdx.x & 31;
    int t = blockIdx.x * 4 + warp;
    const float* hr = h + (long long)t * EMB;
    float lg[N_EXP];
    #pragma unroll
    for (int e = 0; e < N_EXP; e++) {
        float p = 0.f;
        for (int d = lane; d < EMB; d += 32) p += hr[d] * rw[e * EMB + d];
        #pragma unroll
        for (int o = 16; o; o >>= 1) p += __shfl_xor_sync(0xffffffffu, p, o);
        lg[e] = __shfl_sync(0xffffffffu, p, 0);
    }
    if (lane == 0) {
        int i1 = 0;
        #pragma unroll
        for (int e = 1; e < N_EXP; e++) if (lg[e] > lg[i1]) i1 = e;
        int i2 = -1;
        #pragma unroll
        for (int e = 0; e < N_EXP; e++) {
            if (e == i1) continue;
            if (i2 < 0 || lg[e] > lg[i2]) i2 = e;
        }
        float e1 = expf(lg[i2] - lg[i1]);
        float w0 = 1.f / (1.f + e1);
        float w1 = e1 / (1.f + e1);
        g_topk_idx[t*2]   = i1;  g_topk_idx[t*2+1] = i2;
        g_topk_w[t*2]     = w0;  g_topk_w[t*2+1]   = w1;
        atomicAdd(&g_counts[i1], 1);
        atomicAdd(&g_counts[i2], 1);
    }
}

__global__ void offsets_kernel() {
    if (threadIdx.x == 0) {
        int o = 0;
        for (int e = 0; e < N_EXP; e++) {
            g_off[e] = o; g_cursor[e] = o;
            o += g_counts[e];
        }
    }
}

__global__ void scatter_kernel() {
    int id = blockIdx.x * blockDim.x + threadIdx.x;
    if (id >= N_SLOT) return;
    int t = id >> 1;
    int e = g_topk_idx[id];
    int pos = atomicAdd(&g_cursor[e], 1);
    g_slot_token[pos] = t;
    g_slot_of[id] = pos;
}

// ---------------- SiLU(gate)*up over gu[N_SLOT,2048] -> act[N_SLOT,1024] ----------------
__global__ void act_kernel() {
    long long slot = blockIdx.x;
    const float* g = g_gu + slot * (2 * MOE_HID);
    float* a = g_act + slot * MOE_HID;
    for (int d = threadIdx.x; d < MOE_HID; d += blockDim.x) {
        float gt = g[d], up = g[d + MOE_HID];
        a[d] = gt / (1.f + expf(-gt)) * up;
    }
}

// ---------------- combine: out = x1 + w0*expert0 + w1*expert1 ----------------
__global__ void combine_kernel(const float* __restrict__ x1, float* __restrict__ out) {
    int t = blockIdx.x;
    int d4 = threadIdx.x * 4;
    int s0 = g_slot_of[t*2], s1 = g_slot_of[t*2+1];
    float w0 = g_topk_w[t*2], w1 = g_topk_w[t*2+1];
    float4 a = *(const float4*)(x1 + (long long)t * EMB + d4);
    float4 e0 = *(const float4*)(g_outslot + (long long)s0 * EMB + d4);
    float4 e1 = *(const float4*)(g_outslot + (long long)s1 * EMB + d4);
    float4 r;
    r.x = a.x + w0*e0.x + w1*e1.x;
    r.y = a.y + w0*e0.y + w1*e1.y;
    r.z = a.z + w0*e0.z + w1*e1.z;
    r.w = a.w + w0*e0.w + w1*e1.w;
    *(float4*)(out + (long long)t * EMB + d4) = r;
}

// ---------------- launch ----------------
extern "C" void kernel_launch(void* const* d_in, const int* in_sizes, int n_in,
                              void* d_out, int out_size) {
    const float* x        = (const float*)d_in[0];
    const int*   pos_ids  = (const int*)d_in[1];
    // d_in[2] attn_mask: pure causal, handled analytically
    const float* norm1_w  = (const float*)d_in[3];
    const float* norm2_w  = (const float*)d_in[4];
    const float* qn_w     = (const float*)d_in[5];
    const float* kn_w     = (const float*)d_in[6];
    const float* q_w      = (const float*)d_in[7];
    const float* k_w      = (const float*)d_in[8];
    const float* v_w      = (const float*)d_in[9];
    const float* o_w      = (const float*)d_in[10];
    const float* router_w = (const float*)d_in[11];
    const float* gate_up  = (const float*)d_in[12];
    const float* down     = (const float*)d_in[13];
    float* out = (float*)d_out;

    float *p_h1, *p_q, *p_k, *p_v, *p_ctx, *p_x1, *p_h2, *p_gu, *p_act, *p_outslot;
    int *p_off, *p_cnt, *p_slot_token;
    cudaGetSymbolAddress((void**)&p_h1, g_h1);
    cudaGetSymbolAddress((void**)&p_q, g_q);
    cudaGetSymbolAddress((void**)&p_k, g_k);
    cudaGetSymbolAddress((void**)&p_v, g_v);
    cudaGetSymbolAddress((void**)&p_ctx, g_ctx);
    cudaGetSymbolAddress((void**)&p_x1, g_x1);
    cudaGetSymbolAddress((void**)&p_h2, g_h2);
    cudaGetSymbolAddress((void**)&p_gu, g_gu);
    cudaGetSymbolAddress((void**)&p_act, g_act);
    cudaGetSymbolAddress((void**)&p_outslot, g_outslot);
    cudaGetSymbolAddress((void**)&p_off, g_off);
    cudaGetSymbolAddress((void**)&p_cnt, g_counts);
    cudaGetSymbolAddress((void**)&p_slot_token, g_slot_token);

    // 1) pre-attention norm
    rmsnorm_kernel<<<T_TOK, 256>>>(x, norm1_w, p_h1);

    // 2) Q/K/V projections
    gemm_kernel<<<dim3(QDIM/BN,  T_TOK/BM, 1), 256>>>(p_h1, q_w, p_q, T_TOK, QDIM,  EMB, nullptr, nullptr, nullptr, nullptr, 0);
    gemm_kernel<<<dim3(KVDIM/BN, T_TOK/BM, 1), 256>>>(p_h1, k_w, p_k, T_TOK, KVDIM, EMB, nullptr, nullptr, nullptr, nullptr, 0);
    gemm_kernel<<<dim3(KVDIM/BN, T_TOK/BM, 1), 256>>>(p_h1, v_w, p_v, T_TOK, KVDIM, EMB, nullptr, nullptr, nullptr, nullptr, 0);

    // 3) per-head RMSNorm + RoPE (in place)
    qknorm_rope_kernel<<<dim3(T_TOK, N_HEADS), HEAD_DIM>>>(p_q, qn_w, pos_ids, N_HEADS);
    qknorm_rope_kernel<<<dim3(T_TOK, N_KV),    HEAD_DIM>>>(p_k, kn_w, pos_ids, N_KV);

    // 4) causal GQA attention
    attn_kernel<<<dim3(SEQ/QT, N_HEADS, BATCH), 128>>>(p_q, p_k, p_v, p_ctx);

    // 5) output projection + residual
    gemm_kernel<<<dim3(EMB/BN, T_TOK/BM, 1), 256>>>(p_ctx, o_w, p_x1, T_TOK, EMB, QDIM, x, nullptr, nullptr, nullptr, 0);

    // 6) pre-MoE norm
    rmsnorm_kernel<<<T_TOK, 256>>>(p_x1, norm2_w, p_h2);

    // 7) routing (top-2) + expert grouping
    reset_kernel<<<1, 32>>>();
    router_kernel<<<T_TOK/4, 128>>>(p_h2, router_w);
    offsets_kernel<<<1, 32>>>();
    scatter_kernel<<<(N_SLOT + 255)/256, 256>>>();

    // 8) expert gate_up GEMM (gathered rows), worst-case grid w/ device-side early exit
    gemm_kernel<<<dim3((2*MOE_HID)/BN, N_SLOT/BM, N_EXP), 256>>>(
        p_h2, gate_up, p_gu, N_SLOT, 2*MOE_HID, EMB,
        nullptr, p_off, p_cnt, p_slot_token, (long long)(2*MOE_HID)*EMB);

    // 9) SiLU(gate)*up
    act_kernel<<<N_SLOT, 256>>>();

    // 10) expert down GEMM (contiguous per-expert rows)
    gemm_kernel<<<dim3(EMB/BN, N_SLOT/BM, N_EXP), 256>>>(
        p_act, down, p_outslot, N_SLOT, EMB, MOE_HID,
        nullptr, p_off, p_cnt, nullptr, (long long)EMB*MOE_HID);

    // 11) weighted combine + residual
    combine_kernel<<<T_TOK, 256>>>(p_x1, out);

    (void)in_sizes; (void)n_in; (void)out_size;
}

// round 3
// speedup vs baseline: 1.7811x; 1.7811x over previous
#include <cuda_runtime.h>
#include <cuda_bf16.h>
#include <mma.h>
#include <math.h>

using namespace nvcuda;

// ---------------- problem constants ----------------
#define EMB      1024
#define N_HEADS  16
#define N_KV     4
#define HEAD_DIM 128
#define N_EXP    8
#define TOP_K    2
#define MOE_HID  1024
#define BATCH    2
#define SEQ      2048
#define T_TOK    (BATCH*SEQ)          // 4096
#define QDIM     (N_HEADS*HEAD_DIM)   // 2048
#define KVDIM    (N_KV*HEAD_DIM)      // 512
#define N_SLOT   (T_TOK*TOP_K)        // 8192
#define EPSV     1e-6f

// ---------------- scratch (device globals; no allocation allowed) ----------------
__device__ float g_h1[T_TOK*EMB];
__device__ float g_q [T_TOK*QDIM];
__device__ float g_k [T_TOK*KVDIM];
__device__ float g_v [T_TOK*KVDIM];
__device__ float g_ctx[T_TOK*QDIM];
__device__ float g_x1[T_TOK*EMB];
__device__ float g_h2[T_TOK*EMB];
__device__ float g_gu[N_SLOT*2*MOE_HID];
__device__ float g_act[N_SLOT*MOE_HID];
__device__ float g_outslot[N_SLOT*EMB];
__device__ int   g_topk_idx[N_SLOT];
__device__ float g_topk_w[N_SLOT];
__device__ int   g_counts[N_EXP];
__device__ int   g_off[N_EXP];
__device__ int   g_cursor[N_EXP];
__device__ int   g_slot_token[N_SLOT];
__device__ int   g_slot_of[N_SLOT];

// ---------------- tf32 error-free split helper ----------------
template <typename Frag>
__device__ __forceinline__ void split_tf32(Frag& hi, Frag& lo) {
    #pragma unroll
    for (int t = 0; t < hi.num_elements; t++) {
        float x = hi.x[t];
        float h = wmma::__float_to_tf32(x);
        hi.x[t] = h;
        lo.x[t] = wmma::__float_to_tf32(x - h);
    }
}

// ---------------- block reduce (sum, broadcast) ----------------
__device__ __forceinline__ float blockReduceSum(float v) {
    __shared__ float sh[32];
    int lane = threadIdx.x & 31;
    int wid  = threadIdx.x >> 5;
    int nw   = blockDim.x >> 5;
    #pragma unroll
    for (int o = 16; o; o >>= 1) v += __shfl_xor_sync(0xffffffffu, v, o);
    if (lane == 0) sh[wid] = v;
    __syncthreads();
    if (threadIdx.x == 0) {
        float s = 0.f;
        for (int i = 0; i < nw; i++) s += sh[i];
        sh[0] = s;
    }
    __syncthreads();
    float r = sh[0];
    __syncthreads();
    return r;
}

// ---------------- RMSNorm over EMB=1024 ----------------
__global__ void rmsnorm_kernel(const float* __restrict__ x, const float* __restrict__ w,
                               float* __restrict__ o) {
    int t = blockIdx.x;
    int d4 = threadIdx.x * 4;
    const float* xr = x + (long long)t * EMB;
    float4 v = *(const float4*)(xr + d4);
    float ss = v.x*v.x + v.y*v.y + v.z*v.z + v.w*v.w;
    ss = blockReduceSum(ss);
    float scale = rsqrtf(ss * (1.0f / EMB) + EPSV);
    float4 wv = *(const float4*)(w + d4);
    float4 r;
    r.x = v.x*scale*wv.x; r.y = v.y*scale*wv.y;
    r.z = v.z*scale*wv.z; r.w = v.w*scale*wv.w;
    *(float4*)(o + (long long)t * EMB + d4) = r;
}

// ---------------- per-head RMSNorm + RoPE (in place) ----------------
__global__ void qknorm_rope_kernel(float* __restrict__ qk, const float* __restrict__ w,
                                   const int* __restrict__ pos_ids, int H) {
    int t = blockIdx.x, h = blockIdx.y, d = threadIdx.x;
    float* base = qk + ((long long)t * H + h) * HEAD_DIM;
    float v = base[d];
    float ss = blockReduceSum(v * v);
    float scale = rsqrtf(ss * (1.0f / HEAD_DIM) + EPSV);
    float nv = v * scale * w[d];
    __shared__ float sh[HEAD_DIM];
    sh[d] = nv;
    __syncthreads();
    int s = t & (SEQ - 1);
    float pos = (float)pos_ids[s];
    int i = d & 63;
    float inv = exp2f(-(float)i * (13.287712379549449f / 64.0f));
    float ang = pos * inv;
    float sn, cs;
    sincosf(ang, &sn, &cs);
    float other = (d < 64) ? -sh[d + 64] : sh[d - 64];
    base[d] = nv * cs + other * sn;
}

// ---------------- 3xtf32 tensor-core GEMM: C[M,N] = gather(A)[M,K] * B[N,K]^T (+res) ----------------
#define GBM 128
#define GBN 128
#define GBK 16
#define BKP 20
__global__ __launch_bounds__(256)
void gemm_tc(const float* __restrict__ A, const float* __restrict__ Bsrc,
             float* __restrict__ C, int Mtotal, int N, int K,
             const float* __restrict__ addres,
             const int* __restrict__ seg_off, const int* __restrict__ seg_cnt,
             const int* __restrict__ rowidx, long long strideB) {
    __shared__ float sA[2][GBM][BKP];
    __shared__ float sB[2][GBN][BKP];

    int z = blockIdx.z;
    int mbase = 0, mcnt = Mtotal;
    if (seg_off) { mbase = seg_off[z]; mcnt = seg_cnt[z]; }
    int tm0 = blockIdx.y * GBM;
    if (tm0 >= mcnt) return;
    int tn0 = blockIdx.x * GBN;
    const float* Bp = Bsrc + (long long)z * strideB;

    int tid = threadIdx.x;
    int wid = tid >> 5;
    int lane = tid & 31;
    int wm = wid & 3;       // warp row 0..3 (32 rows each)
    int wn = wid >> 2;      // warp col 0..1 (64 cols each)

    int lrow = tid >> 1;          // 0..127
    int lc0 = (tid & 1) * 8;      // 0 or 8

    int arowLocal = tm0 + lrow;
    bool avalid = (arowLocal < mcnt);
    long long arow = 0;
    if (avalid) arow = rowidx ? (long long)rowidx[mbase + arowLocal] : (long long)(mbase + arowLocal);
    const float* Aload = A + arow * (long long)K + lc0;
    const float* Bload = Bp + (long long)(tn0 + lrow) * K + lc0;

    wmma::fragment<wmma::accumulator,16,16,8,float> acc[2][4];
    #pragma unroll
    for (int i = 0; i < 2; i++)
        #pragma unroll
        for (int j = 0; j < 4; j++) wmma::fill_fragment(acc[i][j], 0.f);

    int nIter = K / GBK;

    // preload tile 0
    {
        float4 a0 = avalid ? *(const float4*)(Aload)   : make_float4(0,0,0,0);
        float4 a1 = avalid ? *(const float4*)(Aload+4) : make_float4(0,0,0,0);
        float4 b0 = *(const float4*)(Bload);
        float4 b1 = *(const float4*)(Bload+4);
        *(float4*)&sA[0][lrow][lc0]   = a0;
        *(float4*)&sA[0][lrow][lc0+4] = a1;
        *(float4*)&sB[0][lrow][lc0]   = b0;
        *(float4*)&sB[0][lrow][lc0+4] = b1;
    }
    __syncthreads();

    int cur = 0;
    for (int it = 0; it < nIter; it++) {
        float4 a0, a1, b0, b1;
        bool hasNext = (it + 1 < nIter);
        if (hasNext) {
            const float* Ap = Aload + (it+1)*GBK;
            const float* Bq = Bload + (it+1)*GBK;
            a0 = avalid ? *(const float4*)(Ap)   : make_float4(0,0,0,0);
            a1 = avalid ? *(const float4*)(Ap+4) : make_float4(0,0,0,0);
            b0 = *(const float4*)(Bq);
            b1 = *(const float4*)(Bq+4);
        }
        #pragma unroll
        for (int kk = 0; kk < GBK; kk += 8) {
            wmma::fragment<wmma::matrix_a,16,16,8,wmma::precision::tf32,wmma::row_major> ahi[2], alo[2];
            #pragma unroll
            for (int i = 0; i < 2; i++) {
                wmma::load_matrix_sync(ahi[i], &sA[cur][wm*32 + i*16][kk], BKP);
                split_tf32(ahi[i], alo[i]);
            }
            #pragma unroll
            for (int j = 0; j < 4; j++) {
                wmma::fragment<wmma::matrix_b,16,16,8,wmma::precision::tf32,wmma::col_major> bhi, blo;
                wmma::load_matrix_sync(bhi, &sB[cur][wn*64 + j*16][kk], BKP);
                split_tf32(bhi, blo);
                #pragma unroll
                for (int i = 0; i < 2; i++) {
                    wmma::mma_sync(acc[i][j], ahi[i], blo, acc[i][j]);
                    wmma::mma_sync(acc[i][j], alo[i], bhi, acc[i][j]);
                    wmma::mma_sync(acc[i][j], ahi[i], bhi, acc[i][j]);
                }
            }
        }
        if (hasNext) {
            int nxt = cur ^ 1;
            *(float4*)&sA[nxt][lrow][lc0]   = a0;
            *(float4*)&sA[nxt][lrow][lc0+4] = a1;
            *(float4*)&sB[nxt][lrow][lc0]   = b0;
            *(float4*)&sB[nxt][lrow][lc0+4] = b1;
            __syncthreads();
            cur = nxt;
        }
    }

    bool full = (tm0 + GBM <= mcnt);
    if (full) {
        #pragma unroll
        for (int i = 0; i < 2; i++) {
            int grow = tm0 + wm*32 + i*16;
            #pragma unroll
            for (int j = 0; j < 4; j++) {
                long long off = ((long long)(mbase + grow))*N + tn0 + wn*64 + j*16;
                if (addres) {
                    wmma::fragment<wmma::accumulator,16,16,8,float> rf;
                    wmma::load_matrix_sync(rf, addres + off, N, wmma::mem_row_major);
                    #pragma unroll
                    for (int t = 0; t < rf.num_elements; t++) acc[i][j].x[t] += rf.x[t];
                }
                wmma::store_matrix_sync(C + off, acc[i][j], N, wmma::mem_row_major);
            }
        }
    } else {
        __syncthreads();
        float* stage = &sA[0][0][0] + wid * 320;   // 16x20 staging per warp
        #pragma unroll
        for (int i = 0; i < 2; i++) {
            int growb = tm0 + wm*32 + i*16;
            #pragma unroll
            for (int j = 0; j < 4; j++) {
                wmma::store_matrix_sync(stage, acc[i][j], 20, wmma::mem_row_major);
                __syncwarp();
                int gc0 = tn0 + wn*64 + j*16;
                #pragma unroll
                for (int e = 0; e < 8; e++) {
                    int idx = e*32 + lane;
                    int r = idx >> 4, c = idx & 15;
                    int grow = growb + r;
                    if (grow < mcnt) {
                        long long off = ((long long)(mbase + grow))*N + gc0 + c;
                        float vv = stage[r*20 + c];
                        if (addres) vv += addres[off];
                        C[off] = vv;
                    }
                }
                __syncwarp();
            }
        }
    }
}

// ---------------- attention: 3xtf32 wmma flash, 32x32 tiles, 128 thr ----------------
#define AQT 32
#define AKT 32
#define ALD 132
#define SLD 36
#define ATTN_SMEM_FLOATS (4*AQT*ALD + AQT*SLD + 96)

__global__ __launch_bounds__(128)
void attn_tc(const float* __restrict__ Q, const float* __restrict__ K,
             const float* __restrict__ V, float* __restrict__ ctx) {
    extern __shared__ float asmem[];
    float* qs  = asmem;                 // 32x132
    float* Ks  = qs  + AQT*ALD;         // 32x132
    float* Vs  = Ks  + AKT*ALD;         // 32x132
    float* cts = Vs  + AKT*ALD;         // 32x132 ctx accum
    float* sc  = cts + AQT*ALD;         // 32x36 (scores, then P)
    float* msm = sc  + AQT*SLD;
    float* lsm = msm + 32;
    float* fsm = lsm + 32;

    int q0 = SEQ - AQT - blockIdx.x * AQT;   // heavy tiles first
    int h = blockIdx.y, b = blockIdx.z;
    int tid = threadIdx.x;
    int wid = tid >> 5;

    const float scale = 0.08838834764831845f; // 1/sqrt(128)
    long long qbase = ((long long)b*SEQ + q0)*QDIM + (long long)h*HEAD_DIM;

    #pragma unroll
    for (int i = 0; i < 8; i++) {
        int lin = i*128 + tid;
        int r = lin >> 5, c4 = (lin & 31) << 2;
        float4 v = *(const float4*)(Q + qbase + (long long)r*QDIM + c4);
        v.x *= scale; v.y *= scale; v.z *= scale; v.w *= scale;
        *(float4*)&qs[r*ALD + c4] = v;
    }
    for (int i = tid; i < AQT*ALD; i += 128) cts[i] = 0.f;
    if (tid < 32) { msm[tid] = -1e30f; lsm[tid] = 0.f; }
    __syncthreads();

    int kvh = h >> 2;
    const float* Kb = K + (long long)b*SEQ*KVDIM + (long long)kvh*HEAD_DIM;
    const float* Vb = V + (long long)b*SEQ*KVDIM + (long long)kvh*HEAD_DIM;

    int sm0 = (wid >> 1) * 16, sn0 = (wid & 1) * 16;

    for (int t0 = 0; t0 <= q0; t0 += AKT) {
        #pragma unroll
        for (int i = 0; i < 8; i++) {
            int lin = i*128 + tid;
            int r = lin >> 5, c4 = (lin & 31) << 2;
            *(float4*)&Ks[r*ALD + c4] = *(const float4*)(Kb + (long long)(t0+r)*KVDIM + c4);
            *(float4*)&Vs[r*ALD + c4] = *(const float4*)(Vb + (long long)(t0+r)*KVDIM + c4);
        }
        __syncthreads();

        // scores: S = q . K^T (each warp one 16x16 tile), 3xtf32
        {
            wmma::fragment<wmma::accumulator,16,16,8,float> sacc;
            wmma::fill_fragment(sacc, 0.f);
            #pragma unroll
            for (int kk = 0; kk < HEAD_DIM; kk += 8) {
                wmma::fragment<wmma::matrix_a,16,16,8,wmma::precision::tf32,wmma::row_major> ahi, alo;
                wmma::fragment<wmma::matrix_b,16,16,8,wmma::precision::tf32,wmma::col_major> bhi, blo;
                wmma::load_matrix_sync(ahi, &qs[sm0*ALD + kk], ALD);
                split_tf32(ahi, alo);
                wmma::load_matrix_sync(bhi, &Ks[sn0*ALD + kk], ALD);
                split_tf32(bhi, blo);
                wmma::mma_sync(sacc, ahi, blo, sacc);
                wmma::mma_sync(sacc, alo, bhi, sacc);
                wmma::mma_sync(sacc, ahi, bhi, sacc);
            }
            wmma::store_matrix_sync(&sc[sm0*SLD + sn0], sacc, SLD, wmma::mem_row_major);
        }
        __syncthreads();

        // online softmax (layout-agnostic, in smem)
        {
            int r = tid >> 2, sub = tid & 3;
            float v[8]; float mx = -1e30f;
            #pragma unroll
            for (int cc = 0; cc < 8; cc++) {
                int c = sub*8 + cc;
                float s = sc[r*SLD + c];
                v[cc] = (t0 + c <= q0 + r) ? s : -1e30f;
                mx = fmaxf(mx, v[cc]);
            }
            mx = fmaxf(mx, __shfl_xor_sync(0xffffffffu, mx, 1));
            mx = fmaxf(mx, __shfl_xor_sync(0xffffffffu, mx, 2));
            float mold = msm[r];
            float nm = fmaxf(mold, mx);
            float sum = 0.f;
            #pragma unroll
            for (int cc = 0; cc < 8; cc++) {
                float p = expf(v[cc] - nm);
                sc[r*SLD + sub*8 + cc] = p;
                sum += p;
            }
            sum += __shfl_xor_sync(0xffffffffu, sum, 1);
            sum += __shfl_xor_sync(0xffffffffu, sum, 2);
            if (sub == 0) {
                float f = expf(mold - nm);
                fsm[r] = f; msm[r] = nm;
                lsm[r] = lsm[r]*f + sum;
            }
        }
        __syncthreads();

        // rescale ctx rows by f
        for (int i = tid; i < AQT*HEAD_DIM/4; i += 128) {
            int r = i >> 5, c4 = (i & 31) << 2;
            float f = fsm[r];
            float4 cv = *(float4*)&cts[r*ALD + c4];
            cv.x *= f; cv.y *= f; cv.z *= f; cv.w *= f;
            *(float4*)&cts[r*ALD + c4] = cv;
        }
        __syncthreads();

        // ctx += P . V  (each warp owns 32 output dims), 3xtf32
        {
            int n0 = wid * 32;
            #pragma unroll
            for (int mi = 0; mi < 2; mi++) {
                #pragma unroll
                for (int nj = 0; nj < 2; nj++) {
                    wmma::fragment<wmma::accumulator,16,16,8,float> pacc;
                    wmma::load_matrix_sync(pacc, &cts[(mi*16)*ALD + n0 + nj*16], ALD, wmma::mem_row_major);
                    #pragma unroll
                    for (int kk = 0; kk < AKT; kk += 8) {
                        wmma::fragment<wmma::matrix_a,16,16,8,wmma::precision::tf32,wmma::row_major> ahi, alo;
                        wmma::fragment<wmma::matrix_b,16,16,8,wmma::precision::tf32,wmma::row_major> bhi, blo;
                        wmma::load_matrix_sync(ahi, &sc[(mi*16)*SLD + kk], SLD);
                        split_tf32(ahi, alo);
                        wmma::load_matrix_sync(bhi, &Vs[kk*ALD + n0 + nj*16], ALD);
                        split_tf32(bhi, blo);
                        wmma::mma_sync(pacc, ahi, blo, pacc);
                        wmma::mma_sync(pacc, alo, bhi, pacc);
                        wmma::mma_sync(pacc, ahi, bhi, pacc);
                    }
                    wmma::store_matrix_sync(&cts[(mi*16)*ALD + n0 + nj*16], pacc, ALD, wmma::mem_row_major);
                }
            }
        }
        __syncthreads();
    }

    // write out: ctx / l
    for (int i = tid; i < AQT*HEAD_DIM/4; i += 128) {
        int r = i >> 5, c4 = (i & 31) << 2;
        float inv = 1.f / lsm[r];
        float4 cv = *(float4*)&cts[r*ALD + c4];
        cv.x *= inv; cv.y *= inv; cv.z *= inv; cv.w *= inv;
        *(float4*)&ctx[qbase + (long long)r*QDIM + c4] = cv;
    }
}

// ---------------- MoE routing ----------------
__global__ void reset_kernel() {
    if (threadIdx.x < N_EXP) g_counts[threadIdx.x] = 0;
}

__global__ void router_kernel(const float* __restrict__ h, const float* __restrict__ rw) {
    int warp = threadIdx.x >> 5, lane = threadIdx.x & 31;
    int t = blockIdx.x * 4 + warp;
    const float* hr = h + (long long)t * EMB;
    float lg[N_EXP];
    #pragma unroll
    for (int e = 0; e < N_EXP; e++) {
        float p = 0.f;
        for (int d = lane; d < EMB; d += 32) p += hr[d] * rw[e * EMB + d];
        #pragma unroll
        for (int o = 16; o; o >>= 1) p += __shfl_xor_sync(0xffffffffu, p, o);
        lg[e] = __shfl_sync(0xffffffffu, p, 0);
    }
    if (lane == 0) {
        int i1 = 0;
        #pragma unroll
        for (int e = 1; e < N_EXP; e++) if (lg[e] > lg[i1]) i1 = e;
        int i2 = -1;
        #pragma unroll
        for (int e = 0; e < N_EXP; e++) {
            if (e == i1) continue;
            if (i2 < 0 || lg[e] > lg[i2]) i2 = e;
        }
        float e1 = expf(lg[i2] - lg[i1]);
        float w0 = 1.f / (1.f + e1);
        float w1 = e1 / (1.f + e1);
        g_topk_idx[t*2]   = i1;  g_topk_idx[t*2+1] = i2;
        g_topk_w[t*2]     = w0;  g_topk_w[t*2+1]   = w1;
        atomicAdd(&g_counts[i1], 1);
        atomicAdd(&g_counts[i2], 1);
    }
}

__global__ void offsets_kernel() {
    if (threadIdx.x == 0) {
        int o = 0;
        for (int e = 0; e < N_EXP; e++) {
            g_off[e] = o; g_cursor[e] = o;
            o += g_counts[e];
        }
    }
}

__global__ void scatter_kernel() {
    int id = blockIdx.x * blockDim.x + threadIdx.x;
    if (id >= N_SLOT) return;
    int t = id >> 1;
    int e = g_topk_idx[id];
    int pos = atomicAdd(&g_cursor[e], 1);
    g_slot_token[pos] = t;
    g_slot_of[id] = pos;
}

// ---------------- SiLU(gate)*up ----------------
__global__ void act_kernel() {
    long long slot = blockIdx.x;
    const float* g = g_gu + slot * (2 * MOE_HID);
    float* a = g_act + slot * MOE_HID;
    int d4 = threadIdx.x * 4;
    float4 gt = *(const float4*)(g + d4);
    float4 up = *(const float4*)(g + MOE_HID + d4);
    float4 r;
    r.x = gt.x / (1.f + expf(-gt.x)) * up.x;
    r.y = gt.y / (1.f + expf(-gt.y)) * up.y;
    r.z = gt.z / (1.f + expf(-gt.z)) * up.z;
    r.w = gt.w / (1.f + expf(-gt.w)) * up.w;
    *(float4*)(a + d4) = r;
}

// ---------------- combine ----------------
__global__ void combine_kernel(const float* __restrict__ x1, float* __restrict__ out) {
    int t = blockIdx.x;
    int d4 = threadIdx.x * 4;
    int s0 = g_slot_of[t*2], s1 = g_slot_of[t*2+1];
    float w0 = g_topk_w[t*2], w1 = g_topk_w[t*2+1];
    float4 a  = *(const float4*)(x1 + (long long)t * EMB + d4);
    float4 e0 = *(const float4*)(g_outslot + (long long)s0 * EMB + d4);
    float4 e1 = *(const float4*)(g_outslot + (long long)s1 * EMB + d4);
    float4 r;
    r.x = a.x + w0*e0.x + w1*e1.x;
    r.y = a.y + w0*e0.y + w1*e1.y;
    r.z = a.z + w0*e0.z + w1*e1.z;
    r.w = a.w + w0*e0.w + w1*e1.w;
    *(float4*)(out + (long long)t * EMB + d4) = r;
}

// ---------------- launch ----------------
extern "C" void kernel_launch(void* const* d_in, const int* in_sizes, int n_in,
                              void* d_out, int out_size) {
    const float* x        = (const float*)d_in[0];
    const int*   pos_ids  = (const int*)d_in[1];
    const float* norm1_w  = (const float*)d_in[3];
    const float* norm2_w  = (const float*)d_in[4];
    const float* qn_w     = (const float*)d_in[5];
    const float* kn_w     = (const float*)d_in[6];
    const float* q_w      = (const float*)d_in[7];
    const float* k_w      = (const float*)d_in[8];
    const float* v_w      = (const float*)d_in[9];
    const float* o_w      = (const float*)d_in[10];
    const float* router_w = (const float*)d_in[11];
    const float* gate_up  = (const float*)d_in[12];
    const float* down     = (const float*)d_in[13];
    float* out = (float*)d_out;

    float *p_h1, *p_q, *p_k, *p_v, *p_ctx, *p_x1, *p_h2, *p_gu, *p_act, *p_outslot;
    int *p_off, *p_cnt, *p_slot_token;
    cudaGetSymbolAddress((void**)&p_h1, g_h1);
    cudaGetSymbolAddress((void**)&p_q, g_q);
    cudaGetSymbolAddress((void**)&p_k, g_k);
    cudaGetSymbolAddress((void**)&p_v, g_v);
    cudaGetSymbolAddress((void**)&p_ctx, g_ctx);
    cudaGetSymbolAddress((void**)&p_x1, g_x1);
    cudaGetSymbolAddress((void**)&p_h2, g_h2);
    cudaGetSymbolAddress((void**)&p_gu, g_gu);
    cudaGetSymbolAddress((void**)&p_act, g_act);
    cudaGetSymbolAddress((void**)&p_outslot, g_outslot);
    cudaGetSymbolAddress((void**)&p_off, g_off);
    cudaGetSymbolAddress((void**)&p_cnt, g_counts);
    cudaGetSymbolAddress((void**)&p_slot_token, g_slot_token);

    static int attn_smem_set = 0;
    int attn_smem = ATTN_SMEM_FLOATS * 4;
    if (!attn_smem_set) {
        cudaFuncSetAttribute(attn_tc, cudaFuncAttributeMaxDynamicSharedMemorySize, attn_smem);
        attn_smem_set = 1;
    }

    // 1) pre-attention norm
    rmsnorm_kernel<<<T_TOK, 256>>>(x, norm1_w, p_h1);

    // 2) Q/K/V projections (3xtf32 tensor cores)
    gemm_tc<<<dim3(QDIM/GBN,  T_TOK/GBM, 1), 256>>>(p_h1, q_w, p_q, T_TOK, QDIM,  EMB, nullptr, nullptr, nullptr, nullptr, 0);
    gemm_tc<<<dim3(KVDIM/GBN, T_TOK/GBM, 1), 256>>>(p_h1, k_w, p_k, T_TOK, KVDIM, EMB, nullptr, nullptr, nullptr, nullptr, 0);
    gemm_tc<<<dim3(KVDIM/GBN, T_TOK/GBM, 1), 256>>>(p_h1, v_w, p_v, T_TOK, KVDIM, EMB, nullptr, nullptr, nullptr, nullptr, 0);

    // 3) per-head RMSNorm + RoPE
    qknorm_rope_kernel<<<dim3(T_TOK, N_HEADS), HEAD_DIM>>>(p_q, qn_w, pos_ids, N_HEADS);
    qknorm_rope_kernel<<<dim3(T_TOK, N_KV),    HEAD_DIM>>>(p_k, kn_w, pos_ids, N_KV);

    // 4) causal GQA flash attention (3xtf32 tensor cores)
    attn_tc<<<dim3(SEQ/AQT, N_HEADS, BATCH), 128, attn_smem>>>(p_q, p_k, p_v, p_ctx);

    // 5) output projection + residual
    gemm_tc<<<dim3(EMB/GBN, T_TOK/GBM, 1), 256>>>(p_ctx, o_w, p_x1, T_TOK, EMB, QDIM, x, nullptr, nullptr, nullptr, 0);

    // 6) pre-MoE norm
    rmsnorm_kernel<<<T_TOK, 256>>>(p_x1, norm2_w, p_h2);

    // 7) routing (top-2) + expert grouping
    reset_kernel<<<1, 32>>>();
    router_kernel<<<T_TOK/4, 128>>>(p_h2, router_w);
    offsets_kernel<<<1, 32>>>();
    scatter_kernel<<<(N_SLOT + 255)/256, 256>>>();

    // 8) expert gate_up GEMM (gathered rows)
    gemm_tc<<<dim3((2*MOE_HID)/GBN, N_SLOT/GBM, N_EXP), 256>>>(
        p_h2, gate_up, p_gu, N_SLOT, 2*MOE_HID, EMB,
        nullptr, p_off, p_cnt, p_slot_token, (long long)(2*MOE_HID)*EMB);

    // 9) SiLU(gate)*up
    act_kernel<<<N_SLOT, 256>>>();

    // 10) expert down GEMM (contiguous per-expert rows)
    gemm_tc<<<dim3(EMB/GBN, N_SLOT/GBM, N_EXP), 256>>>(
        p_act, down, p_outslot, N_SLOT, EMB, MOE_HID,
        nullptr, p_off, p_cnt, nullptr, (long long)EMB*MOE_HID);

    // 11) weighted combine + residual
    combine_kernel<<<T_TOK, 256>>>(p_x1, out);

    (void)in_sizes; (void)n_in; (void)out_size;
}

// round 4
// speedup vs baseline: 4.4541x; 2.5007x over previous
#include <cuda_runtime.h>
#include <cuda_bf16.h>
#include <mma.h>
#include <math.h>

using namespace nvcuda;

// ---------------- problem constants ----------------
#define EMB      1024
#define N_HEADS  16
#define N_KV     4
#define HEAD_DIM 128
#define N_EXP    8
#define TOP_K    2
#define MOE_HID  1024
#define BATCH    2
#define SEQ      2048
#define T_TOK    (BATCH*SEQ)          // 4096
#define QDIM     (N_HEADS*HEAD_DIM)   // 2048
#define KVDIM    (N_KV*HEAD_DIM)      // 512
#define N_SLOT   (T_TOK*TOP_K)        // 8192
#define EPSV     1e-6f

typedef __nv_bfloat16 bf16;

// ---------------- scratch (device globals; no allocation allowed) ----------------
__device__ float g_h1[T_TOK*EMB];
__device__ float g_q [T_TOK*QDIM];
__device__ float g_k [T_TOK*KVDIM];
__device__ float g_v [T_TOK*KVDIM];
__device__ float g_ctx[T_TOK*QDIM];
__device__ float g_x1[T_TOK*EMB];
__device__ float g_h2[T_TOK*EMB];
__device__ float g_gu[N_SLOT*2*MOE_HID];
__device__ float g_act[N_SLOT*MOE_HID];
__device__ float g_outslot[N_SLOT*EMB];
__device__ int   g_topk_idx[N_SLOT];
__device__ float g_topk_w[N_SLOT];
__device__ int   g_counts[N_EXP];
__device__ int   g_off[N_EXP];
__device__ int   g_cursor[N_EXP];
__device__ int   g_slot_token[N_SLOT];
__device__ int   g_slot_of[N_SLOT];

// ---------------- bf16 hi/lo split ----------------
__device__ __forceinline__ void split_bf16(float x, bf16& hi, bf16& lo) {
    hi = __float2bfloat16(x);
    lo = __float2bfloat16(x - __bfloat162float(hi));
}

// ---------------- block reduce (sum, broadcast) ----------------
__device__ __forceinline__ float blockReduceSum(float v) {
    __shared__ float sh[32];
    int lane = threadIdx.x & 31;
    int wid  = threadIdx.x >> 5;
    int nw   = blockDim.x >> 5;
    #pragma unroll
    for (int o = 16; o; o >>= 1) v += __shfl_xor_sync(0xffffffffu, v, o);
    if (lane == 0) sh[wid] = v;
    __syncthreads();
    if (threadIdx.x == 0) {
        float s = 0.f;
        for (int i = 0; i < nw; i++) s += sh[i];
        sh[0] = s;
    }
    __syncthreads();
    float r = sh[0];
    __syncthreads();
    return r;
}

// ---------------- RMSNorm over EMB=1024 ----------------
__global__ void rmsnorm_kernel(const float* __restrict__ x, const float* __restrict__ w,
                               float* __restrict__ o) {
    int t = blockIdx.x;
    int d4 = threadIdx.x * 4;
    const float* xr = x + (long long)t * EMB;
    float4 v = *(const float4*)(xr + d4);
    float ss = v.x*v.x + v.y*v.y + v.z*v.z + v.w*v.w;
    ss = blockReduceSum(ss);
    float scale = rsqrtf(ss * (1.0f / EMB) + EPSV);
    float4 wv = *(const float4*)(w + d4);
    float4 r;
    r.x = v.x*scale*wv.x; r.y = v.y*scale*wv.y;
    r.z = v.z*scale*wv.z; r.w = v.w*scale*wv.w;
    *(float4*)(o + (long long)t * EMB + d4) = r;
}

// ---------------- per-head RMSNorm + RoPE (in place) ----------------
__global__ void qknorm_rope_kernel(float* __restrict__ qk, const float* __restrict__ w,
                                   const int* __restrict__ pos_ids, int H) {
    int t = blockIdx.x, h = blockIdx.y, d = threadIdx.x;
    float* base = qk + ((long long)t * H + h) * HEAD_DIM;
    float v = base[d];
    float ss = blockReduceSum(v * v);
    float scale = rsqrtf(ss * (1.0f / HEAD_DIM) + EPSV);
    float nv = v * scale * w[d];
    __shared__ float sh[HEAD_DIM];
    sh[d] = nv;
    __syncthreads();
    int s = t & (SEQ - 1);
    float pos = (float)pos_ids[s];
    int i = d & 63;
    float inv = exp2f(-(float)i * (13.287712379549449f / 64.0f));
    float ang = pos * inv;
    float sn, cs;
    sincosf(ang, &sn, &cs);
    float other = (d < 64) ? -sh[d + 64] : sh[d - 64];
    base[d] = nv * cs + other * sn;
}

// ---------------- bf16x3 tensor-core GEMM: C[M,N] = gather(A)[M,K] * B[N,K]^T (+res) ----------------
#define GBM 128
#define GBN 128
#define GBK 16
#define BKP 24   // bf16 elems per smem row (16 + 8 pad), multiple of 8
#define GEMM_SMEM (8*GBM*BKP*2)   // 8 tiles (A/B x hi/lo x 2 buf) = 49152 B

__global__ __launch_bounds__(256, 2)
void gemm_tc(const float* __restrict__ A, const float* __restrict__ Bsrc,
             float* __restrict__ C, int Mtotal, int N, int K,
             const float* __restrict__ addres,
             const int* __restrict__ seg_off, const int* __restrict__ seg_cnt,
             const int* __restrict__ rowidx, long long strideB) {
    extern __shared__ char gsm[];
    bf16* sAhi = (bf16*)gsm;                 // [2][GBM][BKP]
    bf16* sAlo = sAhi + 2*GBM*BKP;
    bf16* sBhi = sAlo + 2*GBM*BKP;
    bf16* sBlo = sBhi + 2*GBN*BKP;

    int z = blockIdx.z;
    int mbase = 0, mcnt = Mtotal;
    if (seg_off) { mbase = seg_off[z]; mcnt = seg_cnt[z]; }
    int tm0 = blockIdx.y * GBM;
    if (tm0 >= mcnt) return;
    int tn0 = blockIdx.x * GBN;
    const float* Bp = Bsrc + (long long)z * strideB;

    int tid = threadIdx.x;
    int wid = tid >> 5;
    int lane = tid & 31;
    int wm = wid & 3;       // warp row 0..3 (32 rows each)
    int wn = wid >> 2;      // warp col 0..1 (64 cols each)

    int lrow = tid >> 1;          // 0..127
    int lc0 = (tid & 1) * 8;      // 0 or 8

    int arowLocal = tm0 + lrow;
    bool avalid = (arowLocal < mcnt);
    long long arow = 0;
    if (avalid) arow = rowidx ? (long long)rowidx[mbase + arowLocal] : (long long)(mbase + arowLocal);
    const float* Aload = A + arow * (long long)K + lc0;
    const float* Bload = Bp + (long long)(tn0 + lrow) * K + lc0;

    wmma::fragment<wmma::accumulator,16,16,16,float> acc[2][4];
    #pragma unroll
    for (int i = 0; i < 2; i++)
        #pragma unroll
        for (int j = 0; j < 4; j++) wmma::fill_fragment(acc[i][j], 0.f);

    int nIter = K / GBK;

    // convert+store helper via unions
    union Pack { bf16 b[8]; uint4 u; };

    // preload tile 0
    {
        float4 a0 = avalid ? *(const float4*)(Aload)   : make_float4(0,0,0,0);
        float4 a1 = avalid ? *(const float4*)(Aload+4) : make_float4(0,0,0,0);
        float4 b0 = *(const float4*)(Bload);
        float4 b1 = *(const float4*)(Bload+4);
        float af[8] = {a0.x,a0.y,a0.z,a0.w,a1.x,a1.y,a1.z,a1.w};
        float bfv[8] = {b0.x,b0.y,b0.z,b0.w,b1.x,b1.y,b1.z,b1.w};
        Pack Ah, Al, Bh, Bl;
        #pragma unroll
        for (int e = 0; e < 8; e++) {
            split_bf16(af[e],  Ah.b[e], Al.b[e]);
            split_bf16(bfv[e], Bh.b[e], Bl.b[e]);
        }
        *(uint4*)&sAhi[lrow*BKP + lc0] = Ah.u;
        *(uint4*)&sAlo[lrow*BKP + lc0] = Al.u;
        *(uint4*)&sBhi[lrow*BKP + lc0] = Bh.u;
        *(uint4*)&sBlo[lrow*BKP + lc0] = Bl.u;
    }
    __syncthreads();

    int cur = 0;
    for (int it = 0; it < nIter; it++) {
        float4 a0, a1, b0, b1;
        bool hasNext = (it + 1 < nIter);
        if (hasNext) {
            const float* Ap = Aload + (it+1)*GBK;
            const float* Bq = Bload + (it+1)*GBK;
            a0 = avalid ? *(const float4*)(Ap)   : make_float4(0,0,0,0);
            a1 = avalid ? *(const float4*)(Ap+4) : make_float4(0,0,0,0);
            b0 = *(const float4*)(Bq);
            b1 = *(const float4*)(Bq+4);
        }
        {
            int base = cur*GBM*BKP;
            wmma::fragment<wmma::matrix_a,16,16,16,bf16,wmma::row_major> ahi[2], alo[2];
            #pragma unroll
            for (int i = 0; i < 2; i++) {
                wmma::load_matrix_sync(ahi[i], &sAhi[base + (wm*32 + i*16)*BKP], BKP);
                wmma::load_matrix_sync(alo[i], &sAlo[base + (wm*32 + i*16)*BKP], BKP);
            }
            #pragma unroll
            for (int j = 0; j < 4; j++) {
                wmma::fragment<wmma::matrix_b,16,16,16,bf16,wmma::col_major> bhi, blo;
                wmma::load_matrix_sync(bhi, &sBhi[base + (wn*64 + j*16)*BKP], BKP);
                wmma::load_matrix_sync(blo, &sBlo[base + (wn*64 + j*16)*BKP], BKP);
                #pragma unroll
                for (int i = 0; i < 2; i++) {
                    wmma::mma_sync(acc[i][j], ahi[i], blo, acc[i][j]);
                    wmma::mma_sync(acc[i][j], alo[i], bhi, acc[i][j]);
                    wmma::mma_sync(acc[i][j], ahi[i], bhi, acc[i][j]);
                }
            }
        }
        if (hasNext) {
            int nxt = cur ^ 1;
            int nb = nxt*GBM*BKP;
            float af[8] = {a0.x,a0.y,a0.z,a0.w,a1.x,a1.y,a1.z,a1.w};
            float bfv[8] = {b0.x,b0.y,b0.z,b0.w,b1.x,b1.y,b1.z,b1.w};
            Pack Ah, Al, Bh, Bl;
            #pragma unroll
            for (int e = 0; e < 8; e++) {
                split_bf16(af[e],  Ah.b[e], Al.b[e]);
                split_bf16(bfv[e], Bh.b[e], Bl.b[e]);
            }
            __syncthreads();
            *(uint4*)&sAhi[nb + lrow*BKP + lc0] = Ah.u;
            *(uint4*)&sAlo[nb + lrow*BKP + lc0] = Al.u;
            *(uint4*)&sBhi[nb + lrow*BKP + lc0] = Bh.u;
            *(uint4*)&sBlo[nb + lrow*BKP + lc0] = Bl.u;
            __syncthreads();
            cur = nxt;
        }
    }

    bool full = (tm0 + GBM <= mcnt);
    if (full) {
        #pragma unroll
        for (int i = 0; i < 2; i++) {
            int grow = tm0 + wm*32 + i*16;
            #pragma unroll
            for (int j = 0; j < 4; j++) {
                long long off = ((long long)(mbase + grow))*N + tn0 + wn*64 + j*16;
                if (addres) {
                    wmma::fragment<wmma::accumulator,16,16,16,float> rf;
                    wmma::load_matrix_sync(rf, addres + off, N, wmma::mem_row_major);
                    #pragma unroll
                    for (int t = 0; t < rf.num_elements; t++) acc[i][j].x[t] += rf.x[t];
                }
                wmma::store_matrix_sync(C + off, acc[i][j], N, wmma::mem_row_major);
            }
        }
    } else {
        __syncthreads();
        float* stage = (float*)gsm + wid * 320;   // 16x20 staging per warp
        #pragma unroll
        for (int i = 0; i < 2; i++) {
            int growb = tm0 + wm*32 + i*16;
            #pragma unroll
            for (int j = 0; j < 4; j++) {
                wmma::store_matrix_sync(stage, acc[i][j], 20, wmma::mem_row_major);
                __syncwarp();
                int gc0 = tn0 + wn*64 + j*16;
                #pragma unroll
                for (int e = 0; e < 8; e++) {
                    int idx = e*32 + lane;
                    int r = idx >> 4, c = idx & 15;
                    int grow = growb + r;
                    if (grow < mcnt) {
                        long long off = ((long long)(mbase + grow))*N + gc0 + c;
                        float vv = stage[r*20 + c];
                        if (addres) vv += addres[off];
                        C[off] = vv;
                    }
                }
                __syncwarp();
            }
        }
    }
}

// ---------------- attention: bf16x3 wmma flash, 32x32 tiles, 128 thr ----------------
#define AQT 32
#define AKT 32
#define ALB 136   // bf16 tile ld
#define CLD 132   // fp32 ctx ld
#define SLD 36    // fp32 score ld
#define PLD 40    // bf16 P ld
// byte offsets
#define OF_QHI 0
#define OF_QLO (OF_QHI + AQT*ALB*2)
#define OF_KHI (OF_QLO + AQT*ALB*2)
#define OF_KLO (OF_KHI + AKT*ALB*2)
#define OF_VHI (OF_KLO + AKT*ALB*2)
#define OF_VLO (OF_VHI + AKT*ALB*2)
#define OF_CTS (OF_VLO + AKT*ALB*2)
#define OF_SC  (OF_CTS + AQT*CLD*4)
#define OF_PHI (OF_SC  + AQT*SLD*4)
#define OF_PLO (OF_PHI + AQT*PLD*2)
#define OF_MS  (OF_PLO + AQT*PLD*2)
#define OF_LS  (OF_MS + 128)
#define OF_FS  (OF_LS + 128)
#define ATTN_SMEM (OF_FS + 128)

__global__ __launch_bounds__(128)
void attn_tc(const float* __restrict__ Q, const float* __restrict__ K,
             const float* __restrict__ V, float* __restrict__ ctx) {
    extern __shared__ char asm_[];
    bf16* qhi = (bf16*)(asm_ + OF_QHI);
    bf16* qlo = (bf16*)(asm_ + OF_QLO);
    bf16* Khi = (bf16*)(asm_ + OF_KHI);
    bf16* Klo = (bf16*)(asm_ + OF_KLO);
    bf16* Vhi = (bf16*)(asm_ + OF_VHI);
    bf16* Vlo = (bf16*)(asm_ + OF_VLO);
    float* cts = (float*)(asm_ + OF_CTS);
    float* sc  = (float*)(asm_ + OF_SC);
    bf16* phi = (bf16*)(asm_ + OF_PHI);
    bf16* plo = (bf16*)(asm_ + OF_PLO);
    float* msm = (float*)(asm_ + OF_MS);
    float* lsm = (float*)(asm_ + OF_LS);
    float* fsm = (float*)(asm_ + OF_FS);

    int q0 = SEQ - AQT - blockIdx.x * AQT;   // heavy tiles first
    int h = blockIdx.y, b = blockIdx.z;
    int tid = threadIdx.x;
    int wid = tid >> 5;

    const float scale = 0.08838834764831845f; // 1/sqrt(128)
    long long qbase = ((long long)b*SEQ + q0)*QDIM + (long long)h*HEAD_DIM;

    #pragma unroll
    for (int i = 0; i < 8; i++) {
        int lin = i*128 + tid;
        int r = lin >> 5, c4 = (lin & 31) << 2;
        float4 v = *(const float4*)(Q + qbase + (long long)r*QDIM + c4);
        v.x *= scale; v.y *= scale; v.z *= scale; v.w *= scale;
        bf16 h0,l0,h1,l1,h2,l2,h3,l3;
        split_bf16(v.x,h0,l0); split_bf16(v.y,h1,l1);
        split_bf16(v.z,h2,l2); split_bf16(v.w,h3,l3);
        __nv_bfloat162 hh0 = {h0,h1}, hh1 = {h2,h3};
        __nv_bfloat162 ll0 = {l0,l1}, ll1 = {l2,l3};
        *(uint2*)&qhi[r*ALB + c4] = *(uint2*)&hh0;   // 8B store (hh0,hh1 adjacent)
        ((__nv_bfloat162*)&qhi[r*ALB + c4])[1] = hh1;
        *(__nv_bfloat162*)&qlo[r*ALB + c4] = ll0;
        ((__nv_bfloat162*)&qlo[r*ALB + c4])[1] = ll1;
    }
    for (int i = tid; i < AQT*CLD; i += 128) cts[i] = 0.f;
    if (tid < 32) { msm[tid] = -1e30f; lsm[tid] = 0.f; }
    __syncthreads();

    int kvh = h >> 2;
    const float* Kb = K + (long long)b*SEQ*KVDIM + (long long)kvh*HEAD_DIM;
    const float* Vb = V + (long long)b*SEQ*KVDIM + (long long)kvh*HEAD_DIM;

    int sm0 = (wid >> 1) * 16, sn0 = (wid & 1) * 16;

    for (int t0 = 0; t0 <= q0; t0 += AKT) {
        #pragma unroll
        for (int i = 0; i < 8; i++) {
            int lin = i*128 + tid;
            int r = lin >> 5, c4 = (lin & 31) << 2;
            float4 kv = *(const float4*)(Kb + (long long)(t0+r)*KVDIM + c4);
            float4 vv = *(const float4*)(Vb + (long long)(t0+r)*KVDIM + c4);
            bf16 h0,l0,h1,l1,h2,l2,h3,l3;
            split_bf16(kv.x,h0,l0); split_bf16(kv.y,h1,l1);
            split_bf16(kv.z,h2,l2); split_bf16(kv.w,h3,l3);
            __nv_bfloat162 a0 = {h0,h1}, a1 = {h2,h3}, b0 = {l0,l1}, b1 = {l2,l3};
            ((__nv_bfloat162*)&Khi[r*ALB + c4])[0] = a0;
            ((__nv_bfloat162*)&Khi[r*ALB + c4])[1] = a1;
            ((__nv_bfloat162*)&Klo[r*ALB + c4])[0] = b0;
            ((__nv_bfloat162*)&Klo[r*ALB + c4])[1] = b1;
            split_bf16(vv.x,h0,l0); split_bf16(vv.y,h1,l1);
            split_bf16(vv.z,h2,l2); split_bf16(vv.w,h3,l3);
            __nv_bfloat162 c0 = {h0,h1}, c1 = {h2,h3}, d0 = {l0,l1}, d1 = {l2,l3};
            ((__nv_bfloat162*)&Vhi[r*ALB + c4])[0] = c0;
            ((__nv_bfloat162*)&Vhi[r*ALB + c4])[1] = c1;
            ((__nv_bfloat162*)&Vlo[r*ALB + c4])[0] = d0;
            ((__nv_bfloat162*)&Vlo[r*ALB + c4])[1] = d1;
        }
        __syncthreads();

        // scores: S = q . K^T (each warp one 16x16 tile), bf16x3
        {
            wmma::fragment<wmma::accumulator,16,16,16,float> sacc;
            wmma::fill_fragment(sacc, 0.f);
            #pragma unroll
            for (int kk = 0; kk < HEAD_DIM; kk += 16) {
                wmma::fragment<wmma::matrix_a,16,16,16,bf16,wmma::row_major> ahi, alo;
                wmma::fragment<wmma::matrix_b,16,16,16,bf16,wmma::col_major> bhi, blo;
                wmma::load_matrix_sync(ahi, &qhi[sm0*ALB + kk], ALB);
                wmma::load_matrix_sync(alo, &qlo[sm0*ALB + kk], ALB);
                wmma::load_matrix_sync(bhi, &Khi[sn0*ALB + kk], ALB);
                wmma::load_matrix_sync(blo, &Klo[sn0*ALB + kk], ALB);
                wmma::mma_sync(sacc, ahi, blo, sacc);
                wmma::mma_sync(sacc, alo, bhi, sacc);
                wmma::mma_sync(sacc, ahi, bhi, sacc);
            }
            wmma::store_matrix_sync(&sc[sm0*SLD + sn0], sacc, SLD, wmma::mem_row_major);
        }
        __syncthreads();

        // online softmax (layout-agnostic, in smem) ; P -> hi/lo bf16
        {
            int r = tid >> 2, sub = tid & 3;
            float v[8]; float mx = -1e30f;
            #pragma unroll
            for (int cc = 0; cc < 8; cc++) {
                int c = sub*8 + cc;
                float s = sc[r*SLD + c];
                v[cc] = (t0 + c <= q0 + r) ? s : -1e30f;
                mx = fmaxf(mx, v[cc]);
            }
            mx = fmaxf(mx, __shfl_xor_sync(0xffffffffu, mx, 1));
            mx = fmaxf(mx, __shfl_xor_sync(0xffffffffu, mx, 2));
            float mold = msm[r];
            float nm = fmaxf(mold, mx);
            float sum = 0.f;
            #pragma unroll
            for (int cc = 0; cc < 8; cc++) {
                int c = sub*8 + cc;
                float p = expf(v[cc] - nm);
                sum += p;
                bf16 ph, pl;
                split_bf16(p, ph, pl);
                phi[r*PLD + c] = ph;
                plo[r*PLD + c] = pl;
            }
            sum += __shfl_xor_sync(0xffffffffu, sum, 1);
            sum += __shfl_xor_sync(0xffffffffu, sum, 2);
            if (sub == 0) {
                float f = expf(mold - nm);
                fsm[r] = f; msm[r] = nm;
                lsm[r] = lsm[r]*f + sum;
            }
        }
        __syncthreads();

        // rescale ctx rows by f
        for (int i = tid; i < AQT*HEAD_DIM/4; i += 128) {
            int r = i >> 5, c4 = (i & 31) << 2;
            float f = fsm[r];
            float4 cv = *(float4*)&cts[r*CLD + c4];
            cv.x *= f; cv.y *= f; cv.z *= f; cv.w *= f;
            *(float4*)&cts[r*CLD + c4] = cv;
        }
        __syncthreads();

        // ctx += P . V  (each warp owns 32 output dims), bf16x3
        {
            int n0 = wid * 32;
            #pragma unroll
            for (int mi = 0; mi < 2; mi++) {
                #pragma unroll
                for (int nj = 0; nj < 2; nj++) {
                    wmma::fragment<wmma::accumulator,16,16,16,float> pacc;
                    wmma::load_matrix_sync(pacc, &cts[(mi*16)*CLD + n0 + nj*16], CLD, wmma::mem_row_major);
                    #pragma unroll
                    for (int kk = 0; kk < AKT; kk += 16) {
                        wmma::fragment<wmma::matrix_a,16,16,16,bf16,wmma::row_major> ahi, alo;
                        wmma::fragment<wmma::matrix_b,16,16,16,bf16,wmma::row_major> bhi, blo;
                        wmma::load_matrix_sync(ahi, &phi[(mi*16)*PLD + kk], PLD);
                        wmma::load_matrix_sync(alo, &plo[(mi*16)*PLD + kk], PLD);
                        wmma::load_matrix_sync(bhi, &Vhi[kk*ALB + n0 + nj*16], ALB);
                        wmma::load_matrix_sync(blo, &Vlo[kk*ALB + n0 + nj*16], ALB);
                        wmma::mma_sync(pacc, ahi, blo, pacc);
                        wmma::mma_sync(pacc, alo, bhi, pacc);
                        wmma::mma_sync(pacc, ahi, bhi, pacc);
                    }
                    wmma::store_matrix_sync(&cts[(mi*16)*CLD + n0 + nj*16], pacc, CLD, wmma::mem_row_major);
                }
            }
        }
        __syncthreads();
    }

    // write out: ctx / l
    for (int i = tid; i < AQT*HEAD_DIM/4; i += 128) {
        int r = i >> 5, c4 = (i & 31) << 2;
        float inv = 1.f / lsm[r];
        float4 cv = *(float4*)&cts[r*CLD + c4];
        cv.x *= inv; cv.y *= inv; cv.z *= inv; cv.w *= inv;
        *(float4*)&ctx[qbase + (long long)r*QDIM + c4] = cv;
    }
}

// ---------------- MoE routing ----------------
__global__ void reset_kernel() {
    if (threadIdx.x < N_EXP) g_counts[threadIdx.x] = 0;
}

__global__ void router_kernel(const float* __restrict__ h, const float* __restrict__ rw) {
    int warp = threadIdx.x >> 5, lane = threadIdx.x & 31;
    int t = blockIdx.x * 4 + warp;
    const float* hr = h + (long long)t * EMB;
    float lg[N_EXP];
    #pragma unroll
    for (int e = 0; e < N_EXP; e++) {
        float p = 0.f;
        for (int d = lane; d < EMB; d += 32) p += hr[d] * rw[e * EMB + d];
        #pragma unroll
        for (int o = 16; o; o >>= 1) p += __shfl_xor_sync(0xffffffffu, p, o);
        lg[e] = __shfl_sync(0xffffffffu, p, 0);
    }
    if (lane == 0) {
        int i1 = 0;
        #pragma unroll
        for (int e = 1; e < N_EXP; e++) if (lg[e] > lg[i1]) i1 = e;
        int i2 = -1;
        #pragma unroll
        for (int e = 0; e < N_EXP; e++) {
            if (e == i1) continue;
            if (i2 < 0 || lg[e] > lg[i2]) i2 = e;
        }
        float e1 = expf(lg[i2] - lg[i1]);
        float w0 = 1.f / (1.f + e1);
        float w1 = e1 / (1.f + e1);
        g_topk_idx[t*2]   = i1;  g_topk_idx[t*2+1] = i2;
        g_topk_w[t*2]     = w0;  g_topk_w[t*2+1]   = w1;
        atomicAdd(&g_counts[i1], 1);
        atomicAdd(&g_counts[i2], 1);
    }
}

__global__ void offsets_kernel() {
    if (threadIdx.x == 0) {
        int o = 0;
        for (int e = 0; e < N_EXP; e++) {
            g_off[e] = o; g_cursor[e] = o;
            o += g_counts[e];
        }
    }
}

__global__ void scatter_kernel() {
    int id = blockIdx.x * blockDim.x + threadIdx.x;
    if (id >= N_SLOT) return;
    int t = id >> 1;
    int e = g_topk_idx[id];
    int pos = atomicAdd(&g_cursor[e], 1);
    g_slot_token[pos] = t;
    g_slot_of[id] = pos;
}

// ---------------- SiLU(gate)*up ----------------
__global__ void act_kernel() {
    long long slot = blockIdx.x;
    const float* g = g_gu + slot * (2 * MOE_HID);
    float* a = g_act + slot * MOE_HID;
    int d4 = threadIdx.x * 4;
    float4 gt = *(const float4*)(g + d4);
    float4 up = *(const float4*)(g + MOE_HID + d4);
    float4 r;
    r.x = gt.x / (1.f + expf(-gt.x)) * up.x;
    r.y = gt.y / (1.f + expf(-gt.y)) * up.y;
    r.z = gt.z / (1.f + expf(-gt.z)) * up.z;
    r.w = gt.w / (1.f + expf(-gt.w)) * up.w;
    *(float4*)(a + d4) = r;
}

// ---------------- combine ----------------
__global__ void combine_kernel(const float* __restrict__ x1, float* __restrict__ out) {
    int t = blockIdx.x;
    int d4 = threadIdx.x * 4;
    int s0 = g_slot_of[t*2], s1 = g_slot_of[t*2+1];
    float w0 = g_topk_w[t*2], w1 = g_topk_w[t*2+1];
    float4 a  = *(const float4*)(x1 + (long long)t * EMB + d4);
    float4 e0 = *(const float4*)(g_outslot + (long long)s0 * EMB + d4);
    float4 e1 = *(const float4*)(g_outslot + (long long)s1 * EMB + d4);
    float4 r;
    r.x = a.x + w0*e0.x + w1*e1.x;
    r.y = a.y + w0*e0.y + w1*e1.y;
    r.z = a.z + w0*e0.z + w1*e1.z;
    r.w = a.w + w0*e0.w + w1*e1.w;
    *(float4*)(out + (long long)t * EMB + d4) = r;
}

// ---------------- launch ----------------
extern "C" void kernel_launch(void* const* d_in, const int* in_sizes, int n_in,
                              void* d_out, int out_size) {
    const float* x        = (const float*)d_in[0];
    const int*   pos_ids  = (const int*)d_in[1];
    const float* norm1_w  = (const float*)d_in[3];
    const float* norm2_w  = (const float*)d_in[4];
    const float* qn_w     = (const float*)d_in[5];
    const float* kn_w     = (const float*)d_in[6];
    const float* q_w      = (const float*)d_in[7];
    const float* k_w      = (const float*)d_in[8];
    const float* v_w      = (const float*)d_in[9];
    const float* o_w      = (const float*)d_in[10];
    const float* router_w = (const float*)d_in[11];
    const float* gate_up  = (const float*)d_in[12];
    const float* down     = (const float*)d_in[13];
    float* out = (float*)d_out;

    float *p_h1, *p_q, *p_k, *p_v, *p_ctx, *p_x1, *p_h2, *p_gu, *p_act, *p_outslot;
    int *p_off, *p_cnt, *p_slot_token;
    cudaGetSymbolAddress((void**)&p_h1, g_h1);
    cudaGetSymbolAddress((void**)&p_q, g_q);
    cudaGetSymbolAddress((void**)&p_k, g_k);
    cudaGetSymbolAddress((void**)&p_v, g_v);
    cudaGetSymbolAddress((void**)&p_ctx, g_ctx);
    cudaGetSymbolAddress((void**)&p_x1, g_x1);
    cudaGetSymbolAddress((void**)&p_h2, g_h2);
    cudaGetSymbolAddress((void**)&p_gu, g_gu);
    cudaGetSymbolAddress((void**)&p_act, g_act);
    cudaGetSymbolAddress((void**)&p_outslot, g_outslot);
    cudaGetSymbolAddress((void**)&p_off, g_off);
    cudaGetSymbolAddress((void**)&p_cnt, g_counts);
    cudaGetSymbolAddress((void**)&p_slot_token, g_slot_token);

    static int smem_set = 0;
    if (!smem_set) {
        cudaFuncSetAttribute(attn_tc, cudaFuncAttributeMaxDynamicSharedMemorySize, ATTN_SMEM);
        cudaFuncSetAttribute(gemm_tc, cudaFuncAttributeMaxDynamicSharedMemorySize, GEMM_SMEM);
        smem_set = 1;
    }

    // 1) pre-attention norm
    rmsnorm_kernel<<<T_TOK, 256>>>(x, norm1_w, p_h1);

    // 2) Q/K/V projections (bf16x3 tensor cores)
    gemm_tc<<<dim3(QDIM/GBN,  T_TOK/GBM, 1), 256, GEMM_SMEM>>>(p_h1, q_w, p_q, T_TOK, QDIM,  EMB, nullptr, nullptr, nullptr, nullptr, 0);
    gemm_tc<<<dim3(KVDIM/GBN, T_TOK/GBM, 1), 256, GEMM_SMEM>>>(p_h1, k_w, p_k, T_TOK, KVDIM, EMB, nullptr, nullptr, nullptr, nullptr, 0);
    gemm_tc<<<dim3(KVDIM/GBN, T_TOK/GBM, 1), 256, GEMM_SMEM>>>(p_h1, v_w, p_v, T_TOK, KVDIM, EMB, nullptr, nullptr, nullptr, nullptr, 0);

    // 3) per-head RMSNorm + RoPE
    qknorm_rope_kernel<<<dim3(T_TOK, N_HEADS), HEAD_DIM>>>(p_q, qn_w, pos_ids, N_HEADS);
    qknorm_rope_kernel<<<dim3(T_TOK, N_KV),    HEAD_DIM>>>(p_k, kn_w, pos_ids, N_KV);

    // 4) causal GQA flash attention (bf16x3 tensor cores)
    attn_tc<<<dim3(SEQ/AQT, N_HEADS, BATCH), 128, ATTN_SMEM>>>(p_q, p_k, p_v, p_ctx);

    // 5) output projection + residual
    gemm_tc<<<dim3(EMB/GBN, T_TOK/GBM, 1), 256, GEMM_SMEM>>>(p_ctx, o_w, p_x1, T_TOK, EMB, QDIM, x, nullptr, nullptr, nullptr, 0);

    // 6) pre-MoE norm
    rmsnorm_kernel<<<T_TOK, 256>>>(p_x1, norm2_w, p_h2);

    // 7) routing (top-2) + expert grouping
    reset_kernel<<<1, 32>>>();
    router_kernel<<<T_TOK/4, 128>>>(p_h2, router_w);
    offsets_kernel<<<1, 32>>>();
    scatter_kernel<<<(N_SLOT + 255)/256, 256>>>();

    // 8) expert gate_up GEMM (gathered rows)
    gemm_tc<<<dim3((2*MOE_HID)/GBN, N_SLOT/GBM, N_EXP), 256, GEMM_SMEM>>>(
        p_h2, gate_up, p_gu, N_SLOT, 2*MOE_HID, EMB,
        nullptr, p_off, p_cnt, p_slot_token, (long long)(2*MOE_HID)*EMB);

    // 9) SiLU(gate)*up
    act_kernel<<<N_SLOT, 256>>>();

    // 10) expert down GEMM (contiguous per-expert rows)
    gemm_tc<<<dim3(EMB/GBN, N_SLOT/GBM, N_EXP), 256, GEMM_SMEM>>>(
        p_act, down, p_outslot, N_SLOT, EMB, MOE_HID,
        nullptr, p_off, p_cnt, nullptr, (long long)EMB*MOE_HID);

    // 11) weighted combine + residual
    combine_kernel<<<T_TOK, 256>>>(p_x1, out);

    (void)in_sizes; (void)n_in; (void)out_size;
}

// round 5
// speedup vs baseline: 4.5462x; 1.0207x over previous
#include <cuda_runtime.h>
#include <cuda_bf16.h>
#include <mma.h>
#include <math.h>

using namespace nvcuda;

// ---------------- problem constants ----------------
#define EMB      1024
#define N_HEADS  16
#define N_KV     4
#define HEAD_DIM 128
#define N_EXP    8
#define TOP_K    2
#define MOE_HID  1024
#define BATCH    2
#define SEQ      2048
#define T_TOK    (BATCH*SEQ)          // 4096
#define QDIM     (N_HEADS*HEAD_DIM)   // 2048
#define KVDIM    (N_KV*HEAD_DIM)      // 512
#define QKVDIM   (QDIM + 2*KVDIM)     // 3072
#define N_SLOT   (T_TOK*TOP_K)        // 8192
#define EPSV     1e-6f

typedef __nv_bfloat16 bf16;

// ---------------- scratch (device globals; no allocation allowed) ----------------
__device__ float g_h1[T_TOK*EMB];
__device__ float g_qkvw[QKVDIM*EMB];     // packed Q/K/V weights
__device__ float g_qkv[T_TOK*QKVDIM];    // packed Q/K/V activations
__device__ float g_ctx[T_TOK*QDIM];
__device__ float g_x1[T_TOK*EMB];
__device__ float g_h2[T_TOK*EMB];
__device__ float g_gu[N_SLOT*2*MOE_HID];
__device__ float g_act[N_SLOT*MOE_HID];
__device__ float g_outslot[N_SLOT*EMB];
__device__ int   g_topk_idx[N_SLOT];
__device__ float g_topk_w[N_SLOT];
__device__ int   g_counts[N_EXP];
__device__ int   g_off[N_EXP];
__device__ int   g_cursor[N_EXP];
__device__ int   g_slot_token[N_SLOT];
__device__ int   g_slot_of[N_SLOT];

// ---------------- bf16 hi/lo split ----------------
__device__ __forceinline__ void split_bf16(float x, bf16& hi, bf16& lo) {
    hi = __float2bfloat16(x);
    lo = __float2bfloat16(x - __bfloat162float(hi));
}

// ---------------- block reduce (sum, broadcast) ----------------
__device__ __forceinline__ float blockReduceSum(float v) {
    __shared__ float sh[32];
    int lane = threadIdx.x & 31;
    int wid  = threadIdx.x >> 5;
    int nw   = blockDim.x >> 5;
    #pragma unroll
    for (int o = 16; o; o >>= 1) v += __shfl_xor_sync(0xffffffffu, v, o);
    if (lane == 0) sh[wid] = v;
    __syncthreads();
    if (threadIdx.x == 0) {
        float s = 0.f;
        for (int i = 0; i < nw; i++) s += sh[i];
        sh[0] = s;
    }
    __syncthreads();
    float r = sh[0];
    __syncthreads();
    return r;
}

// ---------------- pack QKV weights into one [QKVDIM, EMB] matrix ----------------
__global__ void pack_qkvw_kernel(const float* __restrict__ qw, const float* __restrict__ kw,
                                 const float* __restrict__ vw) {
    int n = blockIdx.x;
    const float* src;
    if (n < QDIM) src = qw + (long long)n * EMB;
    else if (n < QDIM + KVDIM) src = kw + (long long)(n - QDIM) * EMB;
    else src = vw + (long long)(n - QDIM - KVDIM) * EMB;
    int d4 = threadIdx.x * 4;
    *(float4*)(g_qkvw + (long long)n * EMB + d4) = *(const float4*)(src + d4);
}

// ---------------- RMSNorm over EMB=1024 ----------------
__global__ void rmsnorm_kernel(const float* __restrict__ x, const float* __restrict__ w,
                               float* __restrict__ o) {
    int t = blockIdx.x;
    int d4 = threadIdx.x * 4;
    const float* xr = x + (long long)t * EMB;
    float4 v = *(const float4*)(xr + d4);
    float ss = v.x*v.x + v.y*v.y + v.z*v.z + v.w*v.w;
    ss = blockReduceSum(ss);
    float scale = rsqrtf(ss * (1.0f / EMB) + EPSV);
    float4 wv = *(const float4*)(w + d4);
    float4 r;
    r.x = v.x*scale*wv.x; r.y = v.y*scale*wv.y;
    r.z = v.z*scale*wv.z; r.w = v.w*scale*wv.w;
    *(float4*)(o + (long long)t * EMB + d4) = r;
}

// ---------------- per-head RMSNorm + RoPE on packed buffer (in place) ----------------
__global__ void qknorm_rope_kernel(float* __restrict__ buf, const float* __restrict__ w,
                                   const int* __restrict__ pos_ids, int colOff) {
    int t = blockIdx.x, h = blockIdx.y, d = threadIdx.x;
    float* base = buf + (long long)t * QKVDIM + colOff + h * HEAD_DIM;
    float v = base[d];
    float ss = blockReduceSum(v * v);
    float scale = rsqrtf(ss * (1.0f / HEAD_DIM) + EPSV);
    float nv = v * scale * w[d];
    __shared__ float sh[HEAD_DIM];
    sh[d] = nv;
    __syncthreads();
    int s = t & (SEQ - 1);
    float pos = (float)pos_ids[s];
    int i = d & 63;
    float inv = exp2f(-(float)i * (13.287712379549449f / 64.0f));
    float ang = pos * inv;
    float sn, cs;
    sincosf(ang, &sn, &cs);
    float other = (d < 64) ? -sh[d + 64] : sh[d - 64];
    base[d] = nv * cs + other * sn;
}

// ---------------- bf16x3 tensor-core GEMM: C[M,N] = gather(A)[M,K] * B[N,K]^T (+res) ----------------
#define GBM 128
#define GBN 128
#define GBK 16
#define BKP 24   // bf16 elems per smem row (16 + 8 pad)
#define GEMM_SMEM (8*GBM*BKP*2)   // 49152 B

__global__ __launch_bounds__(256, 2)
void gemm_tc(const float* __restrict__ A, const float* __restrict__ Bsrc,
             float* __restrict__ C, int Mtotal, int N, int K,
             const float* __restrict__ addres,
             const int* __restrict__ seg_off, const int* __restrict__ seg_cnt,
             const int* __restrict__ rowidx, long long strideB) {
    extern __shared__ char gsm[];
    bf16* sAhi = (bf16*)gsm;
    bf16* sAlo = sAhi + 2*GBM*BKP;
    bf16* sBhi = sAlo + 2*GBM*BKP;
    bf16* sBlo = sBhi + 2*GBN*BKP;

    int z = blockIdx.z;
    int mbase = 0, mcnt = Mtotal;
    if (seg_off) { mbase = seg_off[z]; mcnt = seg_cnt[z]; }
    int tm0 = blockIdx.y * GBM;
    if (tm0 >= mcnt) return;
    int tn0 = blockIdx.x * GBN;
    const float* Bp = Bsrc + (long long)z * strideB;

    int tid = threadIdx.x;
    int wid = tid >> 5;
    int lane = tid & 31;
    int wm = wid & 3;
    int wn = wid >> 2;

    int lrow = tid >> 1;
    int lc0 = (tid & 1) * 8;

    int arowLocal = tm0 + lrow;
    bool avalid = (arowLocal < mcnt);
    long long arow = 0;
    if (avalid) arow = rowidx ? (long long)rowidx[mbase + arowLocal] : (long long)(mbase + arowLocal);
    const float* Aload = A + arow * (long long)K + lc0;
    const float* Bload = Bp + (long long)(tn0 + lrow) * K + lc0;

    wmma::fragment<wmma::accumulator,16,16,16,float> acc[2][4];
    #pragma unroll
    for (int i = 0; i < 2; i++)
        #pragma unroll
        for (int j = 0; j < 4; j++) wmma::fill_fragment(acc[i][j], 0.f);

    int nIter = K / GBK;
    union Pack { bf16 b[8]; uint4 u; };

    {
        float4 a0 = avalid ? *(const float4*)(Aload)   : make_float4(0,0,0,0);
        float4 a1 = avalid ? *(const float4*)(Aload+4) : make_float4(0,0,0,0);
        float4 b0 = *(const float4*)(Bload);
        float4 b1 = *(const float4*)(Bload+4);
        float af[8] = {a0.x,a0.y,a0.z,a0.w,a1.x,a1.y,a1.z,a1.w};
        float bfv[8] = {b0.x,b0.y,b0.z,b0.w,b1.x,b1.y,b1.z,b1.w};
        Pack Ah, Al, Bh, Bl;
        #pragma unroll
        for (int e = 0; e < 8; e++) {
            split_bf16(af[e],  Ah.b[e], Al.b[e]);
            split_bf16(bfv[e], Bh.b[e], Bl.b[e]);
        }
        *(uint4*)&sAhi[lrow*BKP + lc0] = Ah.u;
        *(uint4*)&sAlo[lrow*BKP + lc0] = Al.u;
        *(uint4*)&sBhi[lrow*BKP + lc0] = Bh.u;
        *(uint4*)&sBlo[lrow*BKP + lc0] = Bl.u;
    }
    __syncthreads();

    int cur = 0;
    for (int it = 0; it < nIter; it++) {
        float4 a0, a1, b0, b1;
        bool hasNext = (it + 1 < nIter);
        if (hasNext) {
            const float* Ap = Aload + (it+1)*GBK;
            const float* Bq = Bload + (it+1)*GBK;
            a0 = avalid ? *(const float4*)(Ap)   : make_float4(0,0,0,0);
            a1 = avalid ? *(const float4*)(Ap+4) : make_float4(0,0,0,0);
            b0 = *(const float4*)(Bq);
            b1 = *(const float4*)(Bq+4);
        }
        {
            int base = cur*GBM*BKP;
            wmma::fragment<wmma::matrix_a,16,16,16,bf16,wmma::row_major> ahi[2], alo[2];
            #pragma unroll
            for (int i = 0; i < 2; i++) {
                wmma::load_matrix_sync(ahi[i], &sAhi[base + (wm*32 + i*16)*BKP], BKP);
                wmma::load_matrix_sync(alo[i], &sAlo[base + (wm*32 + i*16)*BKP], BKP);
            }
            #pragma unroll
            for (int j = 0; j < 4; j++) {
                wmma::fragment<wmma::matrix_b,16,16,16,bf16,wmma::col_major> bhi, blo;
                wmma::load_matrix_sync(bhi, &sBhi[base + (wn*64 + j*16)*BKP], BKP);
                wmma::load_matrix_sync(blo, &sBlo[base + (wn*64 + j*16)*BKP], BKP);
                #pragma unroll
                for (int i = 0; i < 2; i++) {
                    wmma::mma_sync(acc[i][j], ahi[i], blo, acc[i][j]);
                    wmma::mma_sync(acc[i][j], alo[i], bhi, acc[i][j]);
                    wmma::mma_sync(acc[i][j], ahi[i], bhi, acc[i][j]);
                }
            }
        }
        if (hasNext) {
            int nxt = cur ^ 1;
            int nb = nxt*GBM*BKP;
            float af[8] = {a0.x,a0.y,a0.z,a0.w,a1.x,a1.y,a1.z,a1.w};
            float bfv[8] = {b0.x,b0.y,b0.z,b0.w,b1.x,b1.y,b1.z,b1.w};
            Pack Ah, Al, Bh, Bl;
            #pragma unroll
            for (int e = 0; e < 8; e++) {
                split_bf16(af[e],  Ah.b[e], Al.b[e]);
                split_bf16(bfv[e], Bh.b[e], Bl.b[e]);
            }
            __syncthreads();
            *(uint4*)&sAhi[nb + lrow*BKP + lc0] = Ah.u;
            *(uint4*)&sAlo[nb + lrow*BKP + lc0] = Al.u;
            *(uint4*)&sBhi[nb + lrow*BKP + lc0] = Bh.u;
            *(uint4*)&sBlo[nb + lrow*BKP + lc0] = Bl.u;
            __syncthreads();
            cur = nxt;
        }
    }

    bool full = (tm0 + GBM <= mcnt);
    if (full) {
        #pragma unroll
        for (int i = 0; i < 2; i++) {
            int grow = tm0 + wm*32 + i*16;
            #pragma unroll
            for (int j = 0; j < 4; j++) {
                long long off = ((long long)(mbase + grow))*N + tn0 + wn*64 + j*16;
                if (addres) {
                    wmma::fragment<wmma::accumulator,16,16,16,float> rf;
                    wmma::load_matrix_sync(rf, addres + off, N, wmma::mem_row_major);
                    #pragma unroll
                    for (int t = 0; t < rf.num_elements; t++) acc[i][j].x[t] += rf.x[t];
                }
                wmma::store_matrix_sync(C + off, acc[i][j], N, wmma::mem_row_major);
            }
        }
    } else {
        __syncthreads();
        float* stage = (float*)gsm + wid * 320;
        #pragma unroll
        for (int i = 0; i < 2; i++) {
            int growb = tm0 + wm*32 + i*16;
            #pragma unroll
            for (int j = 0; j < 4; j++) {
                wmma::store_matrix_sync(stage, acc[i][j], 20, wmma::mem_row_major);
                __syncwarp();
                int gc0 = tn0 + wn*64 + j*16;
                #pragma unroll
                for (int e = 0; e < 8; e++) {
                    int idx = e*32 + lane;
                    int r = idx >> 4, c = idx & 15;
                    int grow = growb + r;
                    if (grow < mcnt) {
                        long long off = ((long long)(mbase + grow))*N + gc0 + c;
                        float vv = stage[r*20 + c];
                        if (addres) vv += addres[off];
                        C[off] = vv;
                    }
                }
                __syncwarp();
            }
        }
    }
}

// ---------------- attention: bf16x3 wmma flash, 64q x 32k tiles, 256 thr ----------------
#define AQT 64
#define AKT 32
#define ALB 136   // bf16 tile ld
#define CLD 132   // fp32 ctx ld
#define SLD 36    // fp32 score ld
#define PLD 40    // bf16 P ld
#define OF_QHI 0
#define OF_QLO (OF_QHI + AQT*ALB*2)
#define OF_KHI (OF_QLO + AQT*ALB*2)
#define OF_KLO (OF_KHI + AKT*ALB*2)
#define OF_VHI (OF_KLO + AKT*ALB*2)
#define OF_VLO (OF_VHI + AKT*ALB*2)
#define OF_CTS (OF_VLO + AKT*ALB*2)
#define OF_SC  (OF_CTS + AQT*CLD*4)
#define OF_PHI (OF_SC  + AQT*SLD*4)
#define OF_PLO (OF_PHI + AQT*PLD*2)
#define OF_MS  (OF_PLO + AQT*PLD*2)
#define OF_LS  (OF_MS + AQT*4)
#define OF_FS  (OF_LS + AQT*4)
#define ATTN_SMEM (OF_FS + AQT*4)

__global__ __launch_bounds__(256)
void attn_tc(const float* __restrict__ QKV, float* __restrict__ ctx) {
    extern __shared__ char asm_[];
    bf16* qhi = (bf16*)(asm_ + OF_QHI);
    bf16* qlo = (bf16*)(asm_ + OF_QLO);
    bf16* Khi = (bf16*)(asm_ + OF_KHI);
    bf16* Klo = (bf16*)(asm_ + OF_KLO);
    bf16* Vhi = (bf16*)(asm_ + OF_VHI);
    bf16* Vlo = (bf16*)(asm_ + OF_VLO);
    float* cts = (float*)(asm_ + OF_CTS);
    float* sc  = (float*)(asm_ + OF_SC);
    bf16* phi = (bf16*)(asm_ + OF_PHI);
    bf16* plo = (bf16*)(asm_ + OF_PLO);
    float* msm = (float*)(asm_ + OF_MS);
    float* lsm = (float*)(asm_ + OF_LS);
    float* fsm = (float*)(asm_ + OF_FS);

    int q0 = SEQ - AQT - blockIdx.x * AQT;   // heavy tiles first
    int h = blockIdx.y, b = blockIdx.z;
    int tid = threadIdx.x;
    int wid = tid >> 5;

    const float scale = 0.08838834764831845f; // 1/sqrt(128)
    const float* Qb = QKV + ((long long)b*SEQ + q0)*QKVDIM + (long long)h*HEAD_DIM;

    #pragma unroll
    for (int i = 0; i < 8; i++) {
        int lin = i*256 + tid;
        int r = lin >> 5, c4 = (lin & 31) << 2;
        float4 v = *(const float4*)(Qb + (long long)r*QKVDIM + c4);
        v.x *= scale; v.y *= scale; v.z *= scale; v.w *= scale;
        bf16 h0,l0,h1,l1,h2,l2,h3,l3;
        split_bf16(v.x,h0,l0); split_bf16(v.y,h1,l1);
        split_bf16(v.z,h2,l2); split_bf16(v.w,h3,l3);
        __nv_bfloat162 hh0 = {h0,h1}, hh1 = {h2,h3};
        __nv_bfloat162 ll0 = {l0,l1}, ll1 = {l2,l3};
        ((__nv_bfloat162*)&qhi[r*ALB + c4])[0] = hh0;
        ((__nv_bfloat162*)&qhi[r*ALB + c4])[1] = hh1;
        ((__nv_bfloat162*)&qlo[r*ALB + c4])[0] = ll0;
        ((__nv_bfloat162*)&qlo[r*ALB + c4])[1] = ll1;
    }
    for (int i = tid; i < AQT*CLD; i += 256) cts[i] = 0.f;
    if (tid < AQT) { msm[tid] = -1e30f; lsm[tid] = 0.f; }
    __syncthreads();

    int kvh = h >> 2;
    const float* Kb = QKV + (long long)b*SEQ*QKVDIM + QDIM + (long long)kvh*HEAD_DIM;
    const float* Vb = QKV + (long long)b*SEQ*QKVDIM + QDIM + KVDIM + (long long)kvh*HEAD_DIM;

    int sm0 = (wid >> 1) * 16, sn0 = (wid & 1) * 16;

    for (int t0 = 0; t0 <= q0 + AQT - AKT; t0 += AKT) {
        #pragma unroll
        for (int i = 0; i < 4; i++) {
            int lin = i*256 + tid;
            int r = lin >> 5, c4 = (lin & 31) << 2;
            float4 kv = *(const float4*)(Kb + (long long)(t0+r)*QKVDIM + c4);
            float4 vv = *(const float4*)(Vb + (long long)(t0+r)*QKVDIM + c4);
            bf16 h0,l0,h1,l1,h2,l2,h3,l3;
            split_bf16(kv.x,h0,l0); split_bf16(kv.y,h1,l1);
            split_bf16(kv.z,h2,l2); split_bf16(kv.w,h3,l3);
            __nv_bfloat162 a0 = {h0,h1}, a1 = {h2,h3}, b0 = {l0,l1}, b1 = {l2,l3};
            ((__nv_bfloat162*)&Khi[r*ALB + c4])[0] = a0;
            ((__nv_bfloat162*)&Khi[r*ALB + c4])[1] = a1;
            ((__nv_bfloat162*)&Klo[r*ALB + c4])[0] = b0;
            ((__nv_bfloat162*)&Klo[r*ALB + c4])[1] = b1;
            split_bf16(vv.x,h0,l0); split_bf16(vv.y,h1,l1);
            split_bf16(vv.z,h2,l2); split_bf16(vv.w,h3,l3);
            __nv_bfloat162 c0 = {h0,h1}, c1 = {h2,h3}, d0 = {l0,l1}, d1 = {l2,l3};
            ((__nv_bfloat162*)&Vhi[r*ALB + c4])[0] = c0;
            ((__nv_bfloat162*)&Vhi[r*ALB + c4])[1] = c1;
            ((__nv_bfloat162*)&Vlo[r*ALB + c4])[0] = d0;
            ((__nv_bfloat162*)&Vlo[r*ALB + c4])[1] = d1;
        }
        __syncthreads();

        // scores: S[64x32] = q . K^T, 8 warps -> 8 16x16 tiles, bf16x3
        {
            wmma::fragment<wmma::accumulator,16,16,16,float> sacc;
            wmma::fill_fragment(sacc, 0.f);
            int smr = (wid >> 1) * 16;   // 0..3 row tile
            int snc = (wid & 1) * 16;    // 0..1 col tile
            #pragma unroll
            for (int kk = 0; kk < HEAD_DIM; kk += 16) {
                wmma::fragment<wmma::matrix_a,16,16,16,bf16,wmma::row_major> ahi, alo;
                wmma::fragment<wmma::matrix_b,16,16,16,bf16,wmma::col_major> bhi, blo;
                wmma::load_matrix_sync(ahi, &qhi[smr*ALB + kk], ALB);
                wmma::load_matrix_sync(alo, &qlo[smr*ALB + kk], ALB);
                wmma::load_matrix_sync(bhi, &Khi[snc*ALB + kk], ALB);
                wmma::load_matrix_sync(blo, &Klo[snc*ALB + kk], ALB);
                wmma::mma_sync(sacc, ahi, blo, sacc);
                wmma::mma_sync(sacc, alo, bhi, sacc);
                wmma::mma_sync(sacc, ahi, bhi, sacc);
            }
            wmma::store_matrix_sync(&sc[smr*SLD + snc], sacc, SLD, wmma::mem_row_major);
        }
        __syncthreads();

        // online softmax (layout-agnostic, in smem); P -> hi/lo bf16
        {
            int r = tid >> 2, sub = tid & 3;
            float v[8]; float mx = -1e30f;
            #pragma unroll
            for (int cc = 0; cc < 8; cc++) {
                int c = sub*8 + cc;
                float s = sc[r*SLD + c];
                v[cc] = (t0 + c <= q0 + r) ? s : -1e30f;
                mx = fmaxf(mx, v[cc]);
            }
            mx = fmaxf(mx, __shfl_xor_sync(0xffffffffu, mx, 1));
            mx = fmaxf(mx, __shfl_xor_sync(0xffffffffu, mx, 2));
            float mold = msm[r];
            float nm = fmaxf(mold, mx);
            float sum = 0.f;
            #pragma unroll
            for (int cc = 0; cc < 8; cc++) {
                int c = sub*8 + cc;
                float p = expf(v[cc] - nm);
                sum += p;
                bf16 ph, pl;
                split_bf16(p, ph, pl);
                phi[r*PLD + c] = ph;
                plo[r*PLD + c] = pl;
            }
            sum += __shfl_xor_sync(0xffffffffu, sum, 1);
            sum += __shfl_xor_sync(0xffffffffu, sum, 2);
            if (sub == 0) {
                float f = expf(mold - nm);
                fsm[r] = f; msm[r] = nm;
                lsm[r] = lsm[r]*f + sum;
            }
        }
        __syncthreads();

        // rescale ctx rows by f
        #pragma unroll
        for (int i = 0; i < 8; i++) {
            int lin = i*256 + tid;
            int r = lin >> 5, c4 = (lin & 31) << 2;
            float f = fsm[r];
            float4 cv = *(float4*)&cts[r*CLD + c4];
            cv.x *= f; cv.y *= f; cv.z *= f; cv.w *= f;
            *(float4*)&cts[r*CLD + c4] = cv;
        }
        __syncthreads();

        // ctx += P . V  (warp -> 16 rows x 64 cols), bf16x3
        {
            int mi = wid >> 1;           // 0..3 (16-row group)
            int n0 = (wid & 1) * 64;     // 0 or 64
            #pragma unroll
            for (int nj = 0; nj < 4; nj++) {
                wmma::fragment<wmma::accumulator,16,16,16,float> pacc;
                wmma::load_matrix_sync(pacc, &cts[(mi*16)*CLD + n0 + nj*16], CLD, wmma::mem_row_major);
                #pragma unroll
                for (int kk = 0; kk < AKT; kk += 16) {
                    wmma::fragment<wmma::matrix_a,16,16,16,bf16,wmma::row_major> ahi, alo;
                    wmma::fragment<wmma::matrix_b,16,16,16,bf16,wmma::row_major> bhi, blo;
                    wmma::load_matrix_sync(ahi, &phi[(mi*16)*PLD + kk], PLD);
                    wmma::load_matrix_sync(alo, &plo[(mi*16)*PLD + kk], PLD);
                    wmma::load_matrix_sync(bhi, &Vhi[kk*ALB + n0 + nj*16], ALB);
                    wmma::load_matrix_sync(blo, &Vlo[kk*ALB + n0 + nj*16], ALB);
                    wmma::mma_sync(pacc, ahi, blo, pacc);
                    wmma::mma_sync(pacc, alo, bhi, pacc);
                    wmma::mma_sync(pacc, ahi, bhi, pacc);
                }
                wmma::store_matrix_sync(&cts[(mi*16)*CLD + n0 + nj*16], pacc, CLD, wmma::mem_row_major);
            }
        }
        __syncthreads();
    }

    // write out: ctx / l
    long long obase = ((long long)b*SEQ + q0)*QDIM + (long long)h*HEAD_DIM;
    #pragma unroll
    for (int i = 0; i < 8; i++) {
        int lin = i*256 + tid;
        int r = lin >> 5, c4 = (lin & 31) << 2;
        float inv = 1.f / lsm[r];
        float4 cv = *(float4*)&cts[r*CLD + c4];
        cv.x *= inv; cv.y *= inv; cv.z *= inv; cv.w *= inv;
        *(float4*)&ctx[obase + (long long)r*QDIM + c4] = cv;
    }
}

// ---------------- MoE routing ----------------
__global__ void reset_kernel() {
    if (threadIdx.x < N_EXP) g_counts[threadIdx.x] = 0;
}

__global__ void router_kernel(const float* __restrict__ h, const float* __restrict__ rw) {
    int warp = threadIdx.x >> 5, lane = threadIdx.x & 31;
    int t = blockIdx.x * 4 + warp;
    const float* hr = h + (long long)t * EMB;
    float lg[N_EXP];
    #pragma unroll
    for (int e = 0; e < N_EXP; e++) {
        float p = 0.f;
        for (int d = lane; d < EMB; d += 32) p += hr[d] * rw[e * EMB + d];
        #pragma unroll
        for (int o = 16; o; o >>= 1) p += __shfl_xor_sync(0xffffffffu, p, o);
        lg[e] = __shfl_sync(0xffffffffu, p, 0);
    }
    if (lane == 0) {
        int i1 = 0;
        #pragma unroll
        for (int e = 1; e < N_EXP; e++) if (lg[e] > lg[i1]) i1 = e;
        int i2 = -1;
        #pragma unroll
        for (int e = 0; e < N_EXP; e++) {
            if (e == i1) continue;
            if (i2 < 0 || lg[e] > lg[i2]) i2 = e;
        }
        float e1 = expf(lg[i2] - lg[i1]);
        float w0 = 1.f / (1.f + e1);
        float w1 = e1 / (1.f + e1);
        g_topk_idx[t*2]   = i1;  g_topk_idx[t*2+1] = i2;
        g_topk_w[t*2]     = w0;  g_topk_w[t*2+1]   = w1;
        atomicAdd(&g_counts[i1], 1);
        atomicAdd(&g_counts[i2], 1);
    }
}

__global__ void offsets_kernel() {
    if (threadIdx.x == 0) {
        int o = 0;
        for (int e = 0; e < N_EXP; e++) {
            g_off[e] = o; g_cursor[e] = o;
            o += g_counts[e];
        }
    }
}

__global__ void scatter_kernel() {
    int id = blockIdx.x * blockDim.x + threadIdx.x;
    if (id >= N_SLOT) return;
    int t = id >> 1;
    int e = g_topk_idx[id];
    int pos = atomicAdd(&g_cursor[e], 1);
    g_slot_token[pos] = t;
    g_slot_of[id] = pos;
}

// ---------------- SiLU(gate)*up ----------------
__global__ void act_kernel() {
    long long slot = blockIdx.x;
    const float* g = g_gu + slot * (2 * MOE_HID);
    float* a = g_act + slot * MOE_HID;
    int d4 = threadIdx.x * 4;
    float4 gt = *(const float4*)(g + d4);
    float4 up = *(const float4*)(g + MOE_HID + d4);
    float4 r;
    r.x = gt.x / (1.f + expf(-gt.x)) * up.x;
    r.y = gt.y / (1.f + expf(-gt.y)) * up.y;
    r.z = gt.z / (1.f + expf(-gt.z)) * up.z;
    r.w = gt.w / (1.f + expf(-gt.w)) * up.w;
    *(float4*)(a + d4) = r;
}

// ---------------- combine ----------------
__global__ void combine_kernel(const float* __restrict__ x1, float* __restrict__ out) {
    int t = blockIdx.x;
    int d4 = threadIdx.x * 4;
    int s0 = g_slot_of[t*2], s1 = g_slot_of[t*2+1];
    float w0 = g_topk_w[t*2], w1 = g_topk_w[t*2+1];
    float4 a  = *(const float4*)(x1 + (long long)t * EMB + d4);
    float4 e0 = *(const float4*)(g_outslot + (long long)s0 * EMB + d4);
    float4 e1 = *(const float4*)(g_outslot + (long long)s1 * EMB + d4);
    float4 r;
    r.x = a.x + w0*e0.x + w1*e1.x;
    r.y = a.y + w0*e0.y + w1*e1.y;
    r.z = a.z + w0*e0.z + w1*e1.z;
    r.w = a.w + w0*e0.w + w1*e1.w;
    *(float4*)(out + (long long)t * EMB + d4) = r;
}

// ---------------- launch ----------------
extern "C" void kernel_launch(void* const* d_in, const int* in_sizes, int n_in,
                              void* d_out, int out_size) {
    const float* x        = (const float*)d_in[0];
    const int*   pos_ids  = (const int*)d_in[1];
    const float* norm1_w  = (const float*)d_in[3];
    const float* norm2_w  = (const float*)d_in[4];
    const float* qn_w     = (const float*)d_in[5];
    const float* kn_w     = (const float*)d_in[6];
    const float* q_w      = (const float*)d_in[7];
    const float* k_w      = (const float*)d_in[8];
    const float* v_w      = (const float*)d_in[9];
    const float* o_w      = (const float*)d_in[10];
    const float* router_w = (const float*)d_in[11];
    const float* gate_up  = (const float*)d_in[12];
    const float* down     = (const float*)d_in[13];
    float* out = (float*)d_out;

    float *p_h1, *p_qkvw, *p_qkv, *p_ctx, *p_x1, *p_h2, *p_gu, *p_act, *p_outslot;
    int *p_off, *p_cnt, *p_slot_token;
    cudaGetSymbolAddress((void**)&p_h1, g_h1);
    cudaGetSymbolAddress((void**)&p_qkvw, g_qkvw);
    cudaGetSymbolAddress((void**)&p_qkv, g_qkv);
    cudaGetSymbolAddress((void**)&p_ctx, g_ctx);
    cudaGetSymbolAddress((void**)&p_x1, g_x1);
    cudaGetSymbolAddress((void**)&p_h2, g_h2);
    cudaGetSymbolAddress((void**)&p_gu, g_gu);
    cudaGetSymbolAddress((void**)&p_act, g_act);
    cudaGetSymbolAddress((void**)&p_outslot, g_outslot);
    cudaGetSymbolAddress((void**)&p_off, g_off);
    cudaGetSymbolAddress((void**)&p_cnt, g_counts);
    cudaGetSymbolAddress((void**)&p_slot_token, g_slot_token);

    static int smem_set = 0;
    if (!smem_set) {
        cudaFuncSetAttribute(attn_tc, cudaFuncAttributeMaxDynamicSharedMemorySize, ATTN_SMEM);
        cudaFuncSetAttribute(gemm_tc, cudaFuncAttributeMaxDynamicSharedMemorySize, GEMM_SMEM);
        smem_set = 1;
    }

    // 0) pack QKV weights
    pack_qkvw_kernel<<<QKVDIM, 256>>>(q_w, k_w, v_w);

    // 1) pre-attention norm
    rmsnorm_kernel<<<T_TOK, 256>>>(x, norm1_w, p_h1);

    // 2) fused QKV projection (bf16x3 tensor cores)
    gemm_tc<<<dim3(QKVDIM/GBN, T_TOK/GBM, 1), 256, GEMM_SMEM>>>(
        p_h1, p_qkvw, p_qkv, T_TOK, QKVDIM, EMB, nullptr, nullptr, nullptr, nullptr, 0);

    // 3) per-head RMSNorm + RoPE (in place on packed buffer)
    qknorm_rope_kernel<<<dim3(T_TOK, N_HEADS), HEAD_DIM>>>(p_qkv, qn_w, pos_ids, 0);
    qknorm_rope_kernel<<<dim3(T_TOK, N_KV),    HEAD_DIM>>>(p_qkv, kn_w, pos_ids, QDIM);

    // 4) causal GQA flash attention (bf16x3 tensor cores)
    attn_tc<<<dim3(SEQ/AQT, N_HEADS, BATCH), 256, ATTN_SMEM>>>(p_qkv, p_ctx);

    // 5) output projection + residual
    gemm_tc<<<dim3(EMB/GBN, T_TOK/GBM, 1), 256, GEMM_SMEM>>>(p_ctx, o_w, p_x1, T_TOK, EMB, QDIM, x, nullptr, nullptr, nullptr, 0);

    // 6) pre-MoE norm
    rmsnorm_kernel<<<T_TOK, 256>>>(p_x1, norm2_w, p_h2);

    // 7) routing (top-2) + expert grouping
    reset_kernel<<<1, 32>>>();
    router_kernel<<<T_TOK/4, 128>>>(p_h2, router_w);
    offsets_kernel<<<1, 32>>>();
    scatter_kernel<<<(N_SLOT + 255)/256, 256>>>();

    // 8) expert gate_up GEMM (gathered rows)
    gemm_tc<<<dim3((2*MOE_HID)/GBN, N_SLOT/GBM, N_EXP), 256, GEMM_SMEM>>>(
        p_h2, gate_up, p_gu, N_SLOT, 2*MOE_HID, EMB,
        nullptr, p_off, p_cnt, p_slot_token, (long long)(2*MOE_HID)*EMB);

    // 9) SiLU(gate)*up
    act_kernel<<<N_SLOT, 256>>>();

    // 10) expert down GEMM (contiguous per-expert rows)
    gemm_tc<<<dim3(EMB/GBN, N_SLOT/GBM, N_EXP), 256, GEMM_SMEM>>>(
        p_act, down, p_outslot, N_SLOT, EMB, MOE_HID,
        nullptr, p_off, p_cnt, nullptr, (long long)EMB*MOE_HID);

    // 11) weighted combine + residual
    combine_kernel<<<T_TOK, 256>>>(p_x1, out);

    (void)in_sizes; (void)n_in; (void)out_size;
}